// round 1
// baseline (speedup 1.0000x reference)
#include <cuda_runtime.h>

#define BATCH 4
#define CIN   64
#define HID   128
#define PLANE 65536          // 256*256
#define NPIX  262144         // BATCH*PLANE
#define NELEM 33554432       // BATCH*HID*PLANE
#define OUT2  16777216       // BATCH*CIN*PLANE  (offset of prior_up in d_out)

// -------- scratch (static device globals: no allocation allowed) --------
__device__ float g_Wall[384 * 64];   // stacked combined weights, row r=3c+q
__device__ float g_ball[384];        // stacked combined biases
__device__ float g_Aconst[HID];      // -exp(A_param)
__device__ float g_prior[NPIX];      // clipped upsampled prior
__device__ float g_Abar[NELEM];
__device__ float g_bx[NELEM];        // B_bar * x_proj
__device__ float g_sH[NELEM];
__device__ float g_sW[NELEM];

// ============================================================
// K_pre: build combined weights  Wall[3c+0]=W_in[c], [3c+1]=W_delta@W_in,
// [3c+2]=W_B@W_in ; biases likewise ; A_const = -exp(A_param)
// ============================================================
__global__ __launch_bounds__(256) void kpre(
    const float* __restrict__ W_in, const float* __restrict__ b_in,
    const float* __restrict__ W_delta, const float* __restrict__ b_delta,
    const float* __restrict__ W_B, const float* __restrict__ b_B,
    const float* __restrict__ A_param)
{
    int idx = blockIdx.x * 256 + threadIdx.x;
    if (idx < 384 * 64) {
        int r = idx >> 6, k = idx & 63;
        int c = r / 3, q = r - 3 * c;
        float v;
        if (q == 0) {
            v = W_in[c * 64 + k];
        } else {
            const float* Wm = (q == 1) ? W_delta : W_B;
            float s = 0.f;
            #pragma unroll 4
            for (int j = 0; j < 128; j++) s = fmaf(Wm[c * 128 + j], W_in[j * 64 + k], s);
            v = s;
        }
        g_Wall[r * 64 + k] = v;
    } else if (idx < 384 * 64 + 384) {
        int r = idx - 384 * 64;
        int c = r / 3, q = r - 3 * c;
        float v;
        if (q == 0) {
            v = b_in[c];
        } else {
            const float* Wm = (q == 1) ? W_delta : W_B;
            const float* bm = (q == 1) ? b_delta : b_B;
            float s = bm[c];
            #pragma unroll 4
            for (int j = 0; j < 128; j++) s = fmaf(Wm[c * 128 + j], b_in[j], s);
            v = s;
        }
        g_ball[r] = v;
    } else if (idx < 384 * 64 + 384 + HID) {
        int c = idx - (384 * 64 + 384);
        g_Aconst[c] = -expf(A_param[c]);
    }
}

// ============================================================
// K_prior: bilinear (align_corners) 64x64 -> 256x256, clip [-1,1]
// writes g_prior and d_out second tuple element
// ============================================================
__global__ __launch_bounds__(256) void kprior(
    const float* __restrict__ prior, float* __restrict__ out2)
{
    int tid = blockIdx.x * 256 + threadIdx.x;      // 0..NPIX-1
    int bi = tid >> 16;
    int hw = tid & 65535;
    int oy = hw >> 8, ox = hw & 255;

    float fy = (float)(oy * 63) / 255.0f;
    float fx = (float)(ox * 63) / 255.0f;
    int y0 = (int)fy; int y1 = min(y0 + 1, 63);
    int x0 = (int)fx; int x1 = min(x0 + 1, 63);
    float wy = fy - (float)y0;
    float wx = fx - (float)x0;

    const float* p = prior + bi * 4096;
    float v00 = p[y0 * 64 + x0], v10 = p[y1 * 64 + x0];
    float v01 = p[y0 * 64 + x1], v11 = p[y1 * 64 + x1];
    float r0 = v00 * (1.f - wy) + v10 * wy;
    float r1 = v01 * (1.f - wy) + v11 * wy;
    float val = r0 * (1.f - wx) + r1 * wx;
    val = fminf(fmaxf(val, -1.f), 1.f);

    g_prior[tid] = val;
    out2[tid] = val;
}

// ============================================================
// K_proj: fused GEMM (M=384, K=64, N=64px per block) + epilogue:
//   xp, delta_pre, bk_pre -> A_bar, bx
// smem: ws[64][384] (transposed weights), xs[64][64], ps[64]
// ============================================================
#define SMEM_PROJ ((384 * 64 + 64 * 64 + 64) * 4)

__global__ __launch_bounds__(256, 2) void kproj(
    const float* __restrict__ x,
    const float* __restrict__ lam_p,
    const float* __restrict__ alp_p)
{
    extern __shared__ float smem[];
    float* ws = smem;                 // [k][384]
    float* xs = smem + 384 * 64;      // [k][64]
    float* ps = xs + 64 * 64;         // [64]

    int tid = threadIdx.x;
    int pix0 = blockIdx.x * 64;
    int bi = pix0 >> 16;
    int hw0 = pix0 & 65535;

    // load x tile: xs[cin][p]  (global coalesced, no transpose needed)
    const float* xg = x + (size_t)bi * CIN * PLANE + hw0;
    for (int q = tid; q < 64 * 64; q += 256) {
        int c = q >> 6, p = q & 63;
        xs[q] = xg[(size_t)c * PLANE + p];
    }
    // load + transpose weights: read float4 along k, store m-contiguous (conflict-free)
    for (int q = tid; q < 6144; q += 256) {
        int m = q % 384, kc = q / 384;             // kc in 0..15
        float4 w = *(const float4*)&g_Wall[m * 64 + kc * 4];
        ws[(kc * 4 + 0) * 384 + m] = w.x;
        ws[(kc * 4 + 1) * 384 + m] = w.y;
        ws[(kc * 4 + 2) * 384 + m] = w.z;
        ws[(kc * 4 + 3) * 384 + m] = w.w;
    }
    if (tid < 64) ps[tid] = g_prior[pix0 + tid];
    __syncthreads();

    int tc = tid & 7;      // pixel group: pixels tc*8 .. tc*8+7
    int tr = tid >> 3;     // row group : rows   tr*12 .. tr*12+11  (= channels tr*4..+3, 3 rows each)

    float acc[12][8];
    #pragma unroll
    for (int i = 0; i < 12; i++)
        #pragma unroll
        for (int j = 0; j < 8; j++) acc[i][j] = 0.f;

    const float* wsk = ws + tr * 12;
    const float* xsk = xs + tc * 8;
    #pragma unroll 4
    for (int k = 0; k < 64; k++) {
        float4 w0 = *(const float4*)(wsk + k * 384);
        float4 w1 = *(const float4*)(wsk + k * 384 + 4);
        float4 w2 = *(const float4*)(wsk + k * 384 + 8);
        float4 xa = *(const float4*)(xsk + k * 64);
        float4 xb = *(const float4*)(xsk + k * 64 + 4);
        float wv[12] = {w0.x, w0.y, w0.z, w0.w, w1.x, w1.y, w1.z, w1.w,
                        w2.x, w2.y, w2.z, w2.w};
        float xv[8] = {xa.x, xa.y, xa.z, xa.w, xb.x, xb.y, xb.z, xb.w};
        #pragma unroll
        for (int i = 0; i < 12; i++)
            #pragma unroll
            for (int j = 0; j < 8; j++)
                acc[i][j] = fmaf(wv[i], xv[j], acc[i][j]);
    }

    float lam = *lam_p;
    float alp = *alp_p;
    int c0 = tr * 4;
    size_t outbase = (size_t)bi * HID * PLANE + hw0 + tc * 8;

    #pragma unroll
    for (int cc = 0; cc < 4; cc++) {
        int c = c0 + cc;
        float bin = g_ball[3 * c];
        float bdl = g_ball[3 * c + 1];
        float bbb = g_ball[3 * c + 2];
        float Ac = g_Aconst[c];
        float av[8], bxv[8];
        #pragma unroll
        for (int j = 0; j < 8; j++) {
            float p = ps[tc * 8 + j];
            float xp   = acc[3 * cc + 0][j] + bin;
            float dpre = acc[3 * cc + 1][j] + bdl + lam * p;
            // softplus, stable (matches jax: max(x,0)+log1p(exp(-|x|)))
            float delta = fmaxf(dpre, 0.f) + log1pf(__expf(-fabsf(dpre)));
            float bk = (acc[3 * cc + 2][j] + bbb) * (1.f + alp * p);
            av[j]  = __expf(delta * Ac);
            bxv[j] = delta * bk * xp;
        }
        size_t o = outbase + (size_t)c * PLANE;
        *(float4*)&g_Abar[o]     = make_float4(av[0], av[1], av[2], av[3]);
        *(float4*)&g_Abar[o + 4] = make_float4(av[4], av[5], av[6], av[7]);
        *(float4*)&g_bx[o]       = make_float4(bxv[0], bxv[1], bxv[2], bxv[3]);
        *(float4*)&g_bx[o + 4]   = make_float4(bxv[4], bxv[5], bxv[6], bxv[7]);
    }
}

// ============================================================
// K_scanH: scan along H (stride 256), thread per (b,c,col) -> coalesced
// ============================================================
__global__ __launch_bounds__(256) void kscanH()
{
    size_t base = (size_t)blockIdx.x * PLANE + threadIdx.x;   // blockIdx = bc (0..511)
    float h = 0.f;
    #pragma unroll 4
    for (int r = 0; r < 256; r++) {
        size_t idx = base + (size_t)r * 256;
        h = fmaf(g_Abar[idx], h, g_bx[idx]);
        g_sH[idx] = h;
    }
}

// ============================================================
// K_scanW: scan along W. Warp per row; affine (a,b) Kogge-Stone warp scan,
// 8 elems/lane via float4 loads (coalesced).
// ============================================================
__global__ __launch_bounds__(256) void kscanW()
{
    int warp = threadIdx.x >> 5;
    int lane = threadIdx.x & 31;
    int row = blockIdx.x * 8 + warp;              // 0 .. 131071
    size_t base = (size_t)row * 256 + lane * 8;

    float4 a0 = *(const float4*)&g_Abar[base];
    float4 a1 = *(const float4*)&g_Abar[base + 4];
    float4 b0 = *(const float4*)&g_bx[base];
    float4 b1 = *(const float4*)&g_bx[base + 4];
    float a[8] = {a0.x, a0.y, a0.z, a0.w, a1.x, a1.y, a1.z, a1.w};
    float b[8] = {b0.x, b0.y, b0.z, b0.w, b1.x, b1.y, b1.z, b1.w};

    // local composite of 8 elems: h -> Ac*h + Bc
    float Ac = 1.f, Bc = 0.f;
    #pragma unroll
    for (int i = 0; i < 8; i++) {
        Bc = fmaf(a[i], Bc, b[i]);
        Ac = a[i] * Ac;
    }
    // inclusive warp scan of affine composition
    #pragma unroll
    for (int d = 1; d < 32; d <<= 1) {
        float Ap = __shfl_up_sync(0xffffffffu, Ac, d);
        float Bp = __shfl_up_sync(0xffffffffu, Bc, d);
        if (lane >= d) {
            Bc = fmaf(Ac, Bp, Bc);
            Ac = Ac * Ap;
        }
    }
    // incoming state for this lane = exclusive prefix applied to h=0  -> B of prev lane
    float hin = __shfl_up_sync(0xffffffffu, Bc, 1);
    if (lane == 0) hin = 0.f;

    float r[8];
    float h = hin;
    #pragma unroll
    for (int i = 0; i < 8; i++) {
        h = fmaf(a[i], h, b[i]);
        r[i] = h;
    }
    *(float4*)&g_sW[base]     = make_float4(r[0], r[1], r[2], r[3]);
    *(float4*)&g_sW[base + 4] = make_float4(r[4], r[5], r[6], r[7]);
}

// ============================================================
// K_out: out = x + gamma * (W_out @ (sH+sW) + b_out)
// GEMM M=64, K=128, N=64px/block
// ============================================================
#define SMEM_OUT ((128 * 64 + 128 * 64) * 4)

__global__ __launch_bounds__(256, 3) void kout(
    const float* __restrict__ x,
    const float* __restrict__ W_out,
    const float* __restrict__ b_out,
    const float* __restrict__ gam_p,
    float* __restrict__ out)
{
    extern __shared__ float smem[];
    float* wo = smem;                // [k][64]
    float* xsum = smem + 128 * 64;   // [k][64]

    int tid = threadIdx.x;
    int pix0 = blockIdx.x * 64;
    int bi = pix0 >> 16;
    int hw0 = pix0 & 65535;

    // weights transpose: read float4 along k, store m-contiguous
    for (int q = tid; q < 2048; q += 256) {
        int m = q & 63, kc = q >> 6;             // kc 0..31
        float4 w = *(const float4*)&W_out[m * 128 + kc * 4];
        wo[(kc * 4 + 0) * 64 + m] = w.x;
        wo[(kc * 4 + 1) * 64 + m] = w.y;
        wo[(kc * 4 + 2) * 64 + m] = w.z;
        wo[(kc * 4 + 3) * 64 + m] = w.w;
    }
    // scanned sum tile
    size_t sb = (size_t)bi * HID * PLANE + hw0;
    for (int q = tid; q < 128 * 64; q += 256) {
        int c = q >> 6, p = q & 63;
        size_t idx = sb + (size_t)c * PLANE + p;
        xsum[q] = g_sH[idx] + g_sW[idx];
    }
    __syncthreads();

    int tc = tid & 15;    // px group tc*4
    int tr = tid >> 4;    // row group tr*4

    float acc[4][4];
    #pragma unroll
    for (int i = 0; i < 4; i++)
        #pragma unroll
        for (int j = 0; j < 4; j++) acc[i][j] = 0.f;

    const float* wk = wo + tr * 4;
    const float* xk = xsum + tc * 4;
    #pragma unroll 8
    for (int k = 0; k < 128; k++) {
        float4 w = *(const float4*)(wk + k * 64);
        float4 xv = *(const float4*)(xk + k * 64);
        float wv[4] = {w.x, w.y, w.z, w.w};
        float xx[4] = {xv.x, xv.y, xv.z, xv.w};
        #pragma unroll
        for (int i = 0; i < 4; i++)
            #pragma unroll
            for (int j = 0; j < 4; j++)
                acc[i][j] = fmaf(wv[i], xx[j], acc[i][j]);
    }

    float gam = *gam_p;
    #pragma unroll
    for (int i = 0; i < 4; i++) {
        int co = tr * 4 + i;
        float bo = b_out[co];
        size_t base = (size_t)bi * CIN * PLANE + (size_t)co * PLANE + hw0 + tc * 4;
        float4 xg = *(const float4*)&x[base];
        float4 o;
        o.x = fmaf(gam, acc[i][0] + bo, xg.x);
        o.y = fmaf(gam, acc[i][1] + bo, xg.y);
        o.z = fmaf(gam, acc[i][2] + bo, xg.z);
        o.w = fmaf(gam, acc[i][3] + bo, xg.w);
        *(float4*)&out[base] = o;
    }
}

// ============================================================
extern "C" void kernel_launch(void* const* d_in, const int* in_sizes, int n_in,
                              void* d_out, int out_size)
{
    const float* x       = (const float*)d_in[0];
    const float* prior   = (const float*)d_in[1];
    const float* W_in    = (const float*)d_in[2];
    const float* b_in    = (const float*)d_in[3];
    const float* W_out   = (const float*)d_in[4];
    const float* b_out   = (const float*)d_in[5];
    const float* W_delta = (const float*)d_in[6];
    const float* b_delta = (const float*)d_in[7];
    const float* W_B     = (const float*)d_in[8];
    const float* b_B     = (const float*)d_in[9];
    const float* A_param = (const float*)d_in[10];
    const float* lam     = (const float*)d_in[11];
    const float* alp     = (const float*)d_in[12];
    const float* gam     = (const float*)d_in[13];
    float* out = (float*)d_out;

    cudaFuncSetAttribute(kproj, cudaFuncAttributeMaxDynamicSharedMemorySize, SMEM_PROJ);
    cudaFuncSetAttribute(kout, cudaFuncAttributeMaxDynamicSharedMemorySize, SMEM_OUT);

    kpre<<<99, 256>>>(W_in, b_in, W_delta, b_delta, W_B, b_B, A_param);
    kprior<<<NPIX / 256, 256>>>(prior, out + OUT2);
    kproj<<<NPIX / 64, 256, SMEM_PROJ>>>(x, lam, alp);
    kscanH<<<BATCH * HID, 256>>>();
    kscanW<<<(BATCH * HID * 256) / 8, 256>>>();
    kout<<<NPIX / 64, 256, SMEM_OUT>>>(x, W_out, b_out, gam, out);
}

// round 2
// speedup vs baseline: 1.0015x; 1.0015x over previous
#include <cuda_runtime.h>

#define BATCH 4
#define CIN   64
#define HID   128
#define PLANE 65536          // 256*256
#define NPIX  262144         // BATCH*PLANE
#define NELEM 33554432       // BATCH*HID*PLANE
#define OUT2  16777216       // BATCH*CIN*PLANE  (offset of prior_up in d_out)

// -------- scratch (static device globals: no allocation allowed) --------
__device__ float g_Wall[384 * 64];   // stacked combined weights, row r=3c+q
__device__ float g_ball[384];        // stacked combined biases
__device__ float g_Aconst[HID];      // -exp(A_param)
__device__ float g_prior[NPIX];      // clipped upsampled prior
__device__ float g_Abar[NELEM];
__device__ float g_bx[NELEM];        // B_bar * x_proj
__device__ float g_sH[NELEM];
__device__ float g_sW[NELEM];

// ============================================================
// K_pre: build combined weights  Wall[3c+0]=W_in[c], [3c+1]=W_delta@W_in,
// [3c+2]=W_B@W_in ; biases likewise ; A_const = -exp(A_param)
// ============================================================
__global__ __launch_bounds__(256) void kpre(
    const float* __restrict__ W_in, const float* __restrict__ b_in,
    const float* __restrict__ W_delta, const float* __restrict__ b_delta,
    const float* __restrict__ W_B, const float* __restrict__ b_B,
    const float* __restrict__ A_param)
{
    int idx = blockIdx.x * 256 + threadIdx.x;
    if (idx < 384 * 64) {
        int r = idx >> 6, k = idx & 63;
        int c = r / 3, q = r - 3 * c;
        float v;
        if (q == 0) {
            v = W_in[c * 64 + k];
        } else {
            const float* Wm = (q == 1) ? W_delta : W_B;
            float s = 0.f;
            #pragma unroll 4
            for (int j = 0; j < 128; j++) s = fmaf(Wm[c * 128 + j], W_in[j * 64 + k], s);
            v = s;
        }
        g_Wall[r * 64 + k] = v;
    } else if (idx < 384 * 64 + 384) {
        int r = idx - 384 * 64;
        int c = r / 3, q = r - 3 * c;
        float v;
        if (q == 0) {
            v = b_in[c];
        } else {
            const float* Wm = (q == 1) ? W_delta : W_B;
            const float* bm = (q == 1) ? b_delta : b_B;
            float s = bm[c];
            #pragma unroll 4
            for (int j = 0; j < 128; j++) s = fmaf(Wm[c * 128 + j], b_in[j], s);
            v = s;
        }
        g_ball[r] = v;
    } else if (idx < 384 * 64 + 384 + HID) {
        int c = idx - (384 * 64 + 384);
        g_Aconst[c] = -expf(A_param[c]);
    }
}

// ============================================================
// K_prior: bilinear (align_corners) 64x64 -> 256x256, clip [-1,1]
// writes g_prior and d_out second tuple element
// ============================================================
__global__ __launch_bounds__(256) void kprior(
    const float* __restrict__ prior, float* __restrict__ out2)
{
    int tid = blockIdx.x * 256 + threadIdx.x;      // 0..NPIX-1
    int bi = tid >> 16;
    int hw = tid & 65535;
    int oy = hw >> 8, ox = hw & 255;

    float fy = (float)(oy * 63) / 255.0f;
    float fx = (float)(ox * 63) / 255.0f;
    int y0 = (int)fy; int y1 = min(y0 + 1, 63);
    int x0 = (int)fx; int x1 = min(x0 + 1, 63);
    float wy = fy - (float)y0;
    float wx = fx - (float)x0;

    const float* p = prior + bi * 4096;
    float v00 = p[y0 * 64 + x0], v10 = p[y1 * 64 + x0];
    float v01 = p[y0 * 64 + x1], v11 = p[y1 * 64 + x1];
    float r0 = v00 * (1.f - wy) + v10 * wy;
    float r1 = v01 * (1.f - wy) + v11 * wy;
    float val = r0 * (1.f - wx) + r1 * wx;
    val = fminf(fmaxf(val, -1.f), 1.f);

    g_prior[tid] = val;
    out2[tid] = val;
}

// ============================================================
// K_proj: fused GEMM (M=384, K=64, N=64px per block) + epilogue:
//   xp, delta_pre, bk_pre -> A_bar, bx
// smem: ws[64][384] (transposed weights), xs[64][64], ps[64]
// ============================================================
#define SMEM_PROJ ((384 * 64 + 64 * 64 + 64) * 4)

__global__ __launch_bounds__(256, 2) void kproj(
    const float* __restrict__ x,
    const float* __restrict__ lam_p,
    const float* __restrict__ alp_p)
{
    extern __shared__ float smem[];
    float* ws = smem;                 // [k][384]
    float* xs = smem + 384 * 64;      // [k][64]
    float* ps = xs + 64 * 64;         // [64]

    int tid = threadIdx.x;
    int pix0 = blockIdx.x * 64;
    int bi = pix0 >> 16;
    int hw0 = pix0 & 65535;

    // load x tile: xs[cin][p]  (global coalesced, no transpose needed)
    const float* xg = x + (size_t)bi * CIN * PLANE + hw0;
    for (int q = tid; q < 64 * 64; q += 256) {
        int c = q >> 6, p = q & 63;
        xs[q] = xg[(size_t)c * PLANE + p];
    }
    // load + transpose weights: read float4 along k, store m-contiguous (conflict-free)
    for (int q = tid; q < 6144; q += 256) {
        int m = q % 384, kc = q / 384;             // kc in 0..15
        float4 w = *(const float4*)&g_Wall[m * 64 + kc * 4];
        ws[(kc * 4 + 0) * 384 + m] = w.x;
        ws[(kc * 4 + 1) * 384 + m] = w.y;
        ws[(kc * 4 + 2) * 384 + m] = w.z;
        ws[(kc * 4 + 3) * 384 + m] = w.w;
    }
    if (tid < 64) ps[tid] = g_prior[pix0 + tid];
    __syncthreads();

    int tc = tid & 7;      // pixel group: pixels tc*8 .. tc*8+7
    int tr = tid >> 3;     // row group : rows   tr*12 .. tr*12+11  (= channels tr*4..+3, 3 rows each)

    float acc[12][8];
    #pragma unroll
    for (int i = 0; i < 12; i++)
        #pragma unroll
        for (int j = 0; j < 8; j++) acc[i][j] = 0.f;

    const float* wsk = ws + tr * 12;
    const float* xsk = xs + tc * 8;
    #pragma unroll 4
    for (int k = 0; k < 64; k++) {
        float4 w0 = *(const float4*)(wsk + k * 384);
        float4 w1 = *(const float4*)(wsk + k * 384 + 4);
        float4 w2 = *(const float4*)(wsk + k * 384 + 8);
        float4 xa = *(const float4*)(xsk + k * 64);
        float4 xb = *(const float4*)(xsk + k * 64 + 4);
        float wv[12] = {w0.x, w0.y, w0.z, w0.w, w1.x, w1.y, w1.z, w1.w,
                        w2.x, w2.y, w2.z, w2.w};
        float xv[8] = {xa.x, xa.y, xa.z, xa.w, xb.x, xb.y, xb.z, xb.w};
        #pragma unroll
        for (int i = 0; i < 12; i++)
            #pragma unroll
            for (int j = 0; j < 8; j++)
                acc[i][j] = fmaf(wv[i], xv[j], acc[i][j]);
    }

    float lam = *lam_p;
    float alp = *alp_p;
    int c0 = tr * 4;
    size_t outbase = (size_t)bi * HID * PLANE + hw0 + tc * 8;

    #pragma unroll
    for (int cc = 0; cc < 4; cc++) {
        int c = c0 + cc;
        float bin = g_ball[3 * c];
        float bdl = g_ball[3 * c + 1];
        float bbb = g_ball[3 * c + 2];
        float Ac = g_Aconst[c];
        float av[8], bxv[8];
        #pragma unroll
        for (int j = 0; j < 8; j++) {
            float p = ps[tc * 8 + j];
            float xp   = acc[3 * cc + 0][j] + bin;
            float dpre = acc[3 * cc + 1][j] + bdl + lam * p;
            // softplus, stable (matches jax: max(x,0)+log1p(exp(-|x|)))
            float delta = fmaxf(dpre, 0.f) + log1pf(__expf(-fabsf(dpre)));
            float bk = (acc[3 * cc + 2][j] + bbb) * (1.f + alp * p);
            av[j]  = __expf(delta * Ac);
            bxv[j] = delta * bk * xp;
        }
        size_t o = outbase + (size_t)c * PLANE;
        *(float4*)&g_Abar[o]     = make_float4(av[0], av[1], av[2], av[3]);
        *(float4*)&g_Abar[o + 4] = make_float4(av[4], av[5], av[6], av[7]);
        *(float4*)&g_bx[o]       = make_float4(bxv[0], bxv[1], bxv[2], bxv[3]);
        *(float4*)&g_bx[o + 4]   = make_float4(bxv[4], bxv[5], bxv[6], bxv[7]);
    }
}

// ============================================================
// K_scanH: scan along H (stride 256), thread per (b,c,col) -> coalesced
// ============================================================
__global__ __launch_bounds__(256) void kscanH()
{
    size_t base = (size_t)blockIdx.x * PLANE + threadIdx.x;   // blockIdx = bc (0..511)
    float h = 0.f;
    #pragma unroll 4
    for (int r = 0; r < 256; r++) {
        size_t idx = base + (size_t)r * 256;
        h = fmaf(g_Abar[idx], h, g_bx[idx]);
        g_sH[idx] = h;
    }
}

// ============================================================
// K_scanW: scan along W. Warp per row; affine (a,b) Kogge-Stone warp scan,
// 8 elems/lane via float4 loads (coalesced).
// ============================================================
__global__ __launch_bounds__(256) void kscanW()
{
    int warp = threadIdx.x >> 5;
    int lane = threadIdx.x & 31;
    int row = blockIdx.x * 8 + warp;              // 0 .. 131071
    size_t base = (size_t)row * 256 + lane * 8;

    float4 a0 = *(const float4*)&g_Abar[base];
    float4 a1 = *(const float4*)&g_Abar[base + 4];
    float4 b0 = *(const float4*)&g_bx[base];
    float4 b1 = *(const float4*)&g_bx[base + 4];
    float a[8] = {a0.x, a0.y, a0.z, a0.w, a1.x, a1.y, a1.z, a1.w};
    float b[8] = {b0.x, b0.y, b0.z, b0.w, b1.x, b1.y, b1.z, b1.w};

    // local composite of 8 elems: h -> Ac*h + Bc
    float Ac = 1.f, Bc = 0.f;
    #pragma unroll
    for (int i = 0; i < 8; i++) {
        Bc = fmaf(a[i], Bc, b[i]);
        Ac = a[i] * Ac;
    }
    // inclusive warp scan of affine composition
    #pragma unroll
    for (int d = 1; d < 32; d <<= 1) {
        float Ap = __shfl_up_sync(0xffffffffu, Ac, d);
        float Bp = __shfl_up_sync(0xffffffffu, Bc, d);
        if (lane >= d) {
            Bc = fmaf(Ac, Bp, Bc);
            Ac = Ac * Ap;
        }
    }
    // incoming state for this lane = exclusive prefix applied to h=0  -> B of prev lane
    float hin = __shfl_up_sync(0xffffffffu, Bc, 1);
    if (lane == 0) hin = 0.f;

    float r[8];
    float h = hin;
    #pragma unroll
    for (int i = 0; i < 8; i++) {
        h = fmaf(a[i], h, b[i]);
        r[i] = h;
    }
    *(float4*)&g_sW[base]     = make_float4(r[0], r[1], r[2], r[3]);
    *(float4*)&g_sW[base + 4] = make_float4(r[4], r[5], r[6], r[7]);
}

// ============================================================
// K_out: out = x + gamma * (W_out @ (sH+sW) + b_out)
// GEMM M=64, K=128, N=64px/block
// ============================================================
#define SMEM_OUT ((128 * 64 + 128 * 64) * 4)

__global__ __launch_bounds__(256, 3) void kout(
    const float* __restrict__ x,
    const float* __restrict__ W_out,
    const float* __restrict__ b_out,
    const float* __restrict__ gam_p,
    float* __restrict__ out)
{
    extern __shared__ float smem[];
    float* wo = smem;                // [k][64]
    float* xsum = smem + 128 * 64;   // [k][64]

    int tid = threadIdx.x;
    int pix0 = blockIdx.x * 64;
    int bi = pix0 >> 16;
    int hw0 = pix0 & 65535;

    // weights transpose: read float4 along k, store m-contiguous
    for (int q = tid; q < 2048; q += 256) {
        int m = q & 63, kc = q >> 6;             // kc 0..31
        float4 w = *(const float4*)&W_out[m * 128 + kc * 4];
        wo[(kc * 4 + 0) * 64 + m] = w.x;
        wo[(kc * 4 + 1) * 64 + m] = w.y;
        wo[(kc * 4 + 2) * 64 + m] = w.z;
        wo[(kc * 4 + 3) * 64 + m] = w.w;
    }
    // scanned sum tile
    size_t sb = (size_t)bi * HID * PLANE + hw0;
    for (int q = tid; q < 128 * 64; q += 256) {
        int c = q >> 6, p = q & 63;
        size_t idx = sb + (size_t)c * PLANE + p;
        xsum[q] = g_sH[idx] + g_sW[idx];
    }
    __syncthreads();

    int tc = tid & 15;    // px group tc*4
    int tr = tid >> 4;    // row group tr*4

    float acc[4][4];
    #pragma unroll
    for (int i = 0; i < 4; i++)
        #pragma unroll
        for (int j = 0; j < 4; j++) acc[i][j] = 0.f;

    const float* wk = wo + tr * 4;
    const float* xk = xsum + tc * 4;
    #pragma unroll 8
    for (int k = 0; k < 128; k++) {
        float4 w = *(const float4*)(wk + k * 64);
        float4 xv = *(const float4*)(xk + k * 64);
        float wv[4] = {w.x, w.y, w.z, w.w};
        float xx[4] = {xv.x, xv.y, xv.z, xv.w};
        #pragma unroll
        for (int i = 0; i < 4; i++)
            #pragma unroll
            for (int j = 0; j < 4; j++)
                acc[i][j] = fmaf(wv[i], xx[j], acc[i][j]);
    }

    float gam = *gam_p;
    #pragma unroll
    for (int i = 0; i < 4; i++) {
        int co = tr * 4 + i;
        float bo = b_out[co];
        size_t base = (size_t)bi * CIN * PLANE + (size_t)co * PLANE + hw0 + tc * 4;
        float4 xg = *(const float4*)&x[base];
        float4 o;
        o.x = fmaf(gam, acc[i][0] + bo, xg.x);
        o.y = fmaf(gam, acc[i][1] + bo, xg.y);
        o.z = fmaf(gam, acc[i][2] + bo, xg.z);
        o.w = fmaf(gam, acc[i][3] + bo, xg.w);
        *(float4*)&out[base] = o;
    }
}

// ============================================================
extern "C" void kernel_launch(void* const* d_in, const int* in_sizes, int n_in,
                              void* d_out, int out_size)
{
    const float* x       = (const float*)d_in[0];
    const float* prior   = (const float*)d_in[1];
    const float* W_in    = (const float*)d_in[2];
    const float* b_in    = (const float*)d_in[3];
    const float* W_out   = (const float*)d_in[4];
    const float* b_out   = (const float*)d_in[5];
    const float* W_delta = (const float*)d_in[6];
    const float* b_delta = (const float*)d_in[7];
    const float* W_B     = (const float*)d_in[8];
    const float* b_B     = (const float*)d_in[9];
    const float* A_param = (const float*)d_in[10];
    const float* lam     = (const float*)d_in[11];
    const float* alp     = (const float*)d_in[12];
    const float* gam     = (const float*)d_in[13];
    float* out = (float*)d_out;

    cudaFuncSetAttribute(kproj, cudaFuncAttributeMaxDynamicSharedMemorySize, SMEM_PROJ);
    cudaFuncSetAttribute(kout, cudaFuncAttributeMaxDynamicSharedMemorySize, SMEM_OUT);

    kpre<<<99, 256>>>(W_in, b_in, W_delta, b_delta, W_B, b_B, A_param);
    kprior<<<NPIX / 256, 256>>>(prior, out + OUT2);
    kproj<<<NPIX / 64, 256, SMEM_PROJ>>>(x, lam, alp);
    kscanH<<<BATCH * HID, 256>>>();
    kscanW<<<(BATCH * HID * 256) / 8, 256>>>();
    kout<<<NPIX / 64, 256, SMEM_OUT>>>(x, W_out, b_out, gam, out);
}

// round 3
// speedup vs baseline: 1.0581x; 1.0566x over previous
#include <cuda_runtime.h>
#include <cuda_fp16.h>

#define BATCH 4
#define CIN   64
#define HID   128
#define PLANE 65536          // 256*256
#define NPIX  262144         // BATCH*PLANE
#define NELEM 33554432       // BATCH*HID*PLANE
#define OUT2  16777216       // BATCH*CIN*PLANE  (offset of prior_up in d_out)

typedef unsigned long long ull;

// ---------------- f32x2 helpers (packed dual-FMA, sm_103a) ----------------
__device__ __forceinline__ ull pk2(float x, float y) {
    ull r; asm("mov.b64 %0, {%1, %2};" : "=l"(r) : "f"(x), "f"(y)); return r;
}
__device__ __forceinline__ ull fma2(ull a, ull b, ull c) {
    ull d; asm("fma.rn.f32x2 %0, %1, %2, %3;" : "=l"(d) : "l"(a), "l"(b), "l"(c)); return d;
}
__device__ __forceinline__ float2 upk(ull a) {
    float2 r; asm("mov.b64 {%0, %1}, %2;" : "=f"(r.x), "=f"(r.y) : "l"(a)); return r;
}
union F4U { float4 f; ull u[2]; };

// -------- scratch (static device globals: no allocation allowed) --------
__device__ float  g_Wall[384 * 64];   // stacked combined weights, row r=3c+q
__device__ float  g_ball[384];        // stacked combined biases
__device__ float  g_Aconst[HID];      // -exp(A_param)
__device__ float  g_prior[NPIX];      // clipped upsampled prior
__device__ __half g_Abar[NELEM];
__device__ __half g_bx[NELEM];        // B_bar * x_proj
__device__ __half g_sH[NELEM];        // H-scan result
__device__ __half g_s[NELEM];         // sH + sW (fused in kscanW)

// ============================================================
// K_pre: combined weights  Wall[3c+0]=W_in[c], [3c+1]=W_delta@W_in,
// [3c+2]=W_B@W_in ; biases likewise ; A_const = -exp(A_param)
// ============================================================
__global__ __launch_bounds__(256) void kpre(
    const float* __restrict__ W_in, const float* __restrict__ b_in,
    const float* __restrict__ W_delta, const float* __restrict__ b_delta,
    const float* __restrict__ W_B, const float* __restrict__ b_B,
    const float* __restrict__ A_param)
{
    int idx = blockIdx.x * 256 + threadIdx.x;
    if (idx < 384 * 64) {
        int r = idx >> 6, k = idx & 63;
        int c = r / 3, q = r - 3 * c;
        float v;
        if (q == 0) {
            v = W_in[c * 64 + k];
        } else {
            const float* Wm = (q == 1) ? W_delta : W_B;
            float s = 0.f;
            #pragma unroll 4
            for (int j = 0; j < 128; j++) s = fmaf(Wm[c * 128 + j], W_in[j * 64 + k], s);
            v = s;
        }
        g_Wall[r * 64 + k] = v;
    } else if (idx < 384 * 64 + 384) {
        int r = idx - 384 * 64;
        int c = r / 3, q = r - 3 * c;
        float v;
        if (q == 0) {
            v = b_in[c];
        } else {
            const float* Wm = (q == 1) ? W_delta : W_B;
            const float* bm = (q == 1) ? b_delta : b_B;
            float s = bm[c];
            #pragma unroll 4
            for (int j = 0; j < 128; j++) s = fmaf(Wm[c * 128 + j], b_in[j], s);
            v = s;
        }
        g_ball[r] = v;
    } else if (idx < 384 * 64 + 384 + HID) {
        int c = idx - (384 * 64 + 384);
        g_Aconst[c] = -expf(A_param[c]);
    }
}

// ============================================================
// K_prior: bilinear (align_corners) 64x64 -> 256x256, clip [-1,1]
// ============================================================
__global__ __launch_bounds__(256) void kprior(
    const float* __restrict__ prior, float* __restrict__ out2)
{
    int tid = blockIdx.x * 256 + threadIdx.x;
    int bi = tid >> 16;
    int hw = tid & 65535;
    int oy = hw >> 8, ox = hw & 255;

    float fy = (float)(oy * 63) / 255.0f;
    float fx = (float)(ox * 63) / 255.0f;
    int y0 = (int)fy; int y1 = min(y0 + 1, 63);
    int x0 = (int)fx; int x1 = min(x0 + 1, 63);
    float wy = fy - (float)y0;
    float wx = fx - (float)x0;

    const float* p = prior + bi * 4096;
    float v00 = p[y0 * 64 + x0], v10 = p[y1 * 64 + x0];
    float v01 = p[y0 * 64 + x1], v11 = p[y1 * 64 + x1];
    float r0 = v00 * (1.f - wy) + v10 * wy;
    float r1 = v01 * (1.f - wy) + v11 * wy;
    float val = r0 * (1.f - wx) + r1 * wx;
    val = fminf(fmaxf(val, -1.f), 1.f);

    g_prior[tid] = val;
    out2[tid] = val;
}

// ============================================================
// K_proj: fused GEMM (M=384, K=64, 64px/block) via f32x2 + epilogue
// -> A_bar (fp16), bx (fp16)
// ============================================================
#define SMEM_PROJ ((384 * 64 + 64 * 64 + 64) * 4)

__global__ __launch_bounds__(256) void kproj(
    const float* __restrict__ x,
    const float* __restrict__ lam_p,
    const float* __restrict__ alp_p)
{
    extern __shared__ float smem[];
    float* ws = smem;                 // [k][384] m-contiguous
    float* xs = smem + 384 * 64;      // [k][64]
    float* ps = xs + 64 * 64;         // [64]

    int tid = threadIdx.x;
    int pix0 = blockIdx.x * 64;
    int bi = pix0 >> 16;
    int hw0 = pix0 & 65535;

    const float* xg = x + (size_t)bi * CIN * PLANE + hw0;
    for (int q = tid; q < 64 * 64; q += 256) {
        int c = q >> 6, p = q & 63;
        xs[q] = xg[(size_t)c * PLANE + p];
    }
    for (int q = tid; q < 6144; q += 256) {
        int m = q % 384, kc = q / 384;
        float4 w = *(const float4*)&g_Wall[m * 64 + kc * 4];
        ws[(kc * 4 + 0) * 384 + m] = w.x;
        ws[(kc * 4 + 1) * 384 + m] = w.y;
        ws[(kc * 4 + 2) * 384 + m] = w.z;
        ws[(kc * 4 + 3) * 384 + m] = w.w;
    }
    if (tid < 64) ps[tid] = g_prior[pix0 + tid];
    __syncthreads();

    int tc = tid & 7;      // pixel group: 8 px
    int tr = tid >> 3;     // row group : 12 rows (= 4 channels x 3 roles)

    ull acc[6][8];         // row-pairs (2rp,2rp+1) x 8 px, packed f32x2
    #pragma unroll
    for (int i = 0; i < 6; i++)
        #pragma unroll
        for (int j = 0; j < 8; j++) acc[i][j] = 0ULL;

    const float* wsk = ws + tr * 12;
    const float* xsk = xs + tc * 8;
    #pragma unroll 4
    for (int k = 0; k < 64; k++) {
        F4U w0, w1, w2, xa, xb;
        w0.f = *(const float4*)(wsk + k * 384);
        w1.f = *(const float4*)(wsk + k * 384 + 4);
        w2.f = *(const float4*)(wsk + k * 384 + 8);
        xa.f = *(const float4*)(xsk + k * 64);
        xb.f = *(const float4*)(xsk + k * 64 + 4);
        ull wp[6] = {w0.u[0], w0.u[1], w1.u[0], w1.u[1], w2.u[0], w2.u[1]};
        ull xd[8];
        xd[0] = pk2(xa.f.x, xa.f.x); xd[1] = pk2(xa.f.y, xa.f.y);
        xd[2] = pk2(xa.f.z, xa.f.z); xd[3] = pk2(xa.f.w, xa.f.w);
        xd[4] = pk2(xb.f.x, xb.f.x); xd[5] = pk2(xb.f.y, xb.f.y);
        xd[6] = pk2(xb.f.z, xb.f.z); xd[7] = pk2(xb.f.w, xb.f.w);
        #pragma unroll
        for (int i = 0; i < 6; i++)
            #pragma unroll
            for (int j = 0; j < 8; j++)
                acc[i][j] = fma2(wp[i], xd[j], acc[i][j]);
    }

    float lam = *lam_p;
    float alp = *alp_p;
    int c0 = tr * 4;
    size_t outbase = (size_t)bi * HID * PLANE + hw0 + tc * 8;

    // ACCF(i,j): scalar for row i (0..11), pixel j
    #define ACCF(i, j) (((i) & 1) ? upk(acc[(i) >> 1][j]).y : upk(acc[(i) >> 1][j]).x)

    #pragma unroll
    for (int cc = 0; cc < 4; cc++) {
        int c = c0 + cc;
        float bin = g_ball[3 * c];
        float bdl = g_ball[3 * c + 1];
        float bbb = g_ball[3 * c + 2];
        float Ac = g_Aconst[c];
        float av[8], bxv[8];
        #pragma unroll
        for (int j = 0; j < 8; j++) {
            float p = ps[tc * 8 + j];
            float xp   = ACCF(3 * cc + 0, j) + bin;
            float dpre = ACCF(3 * cc + 1, j) + bdl + lam * p;
            float delta = fmaxf(dpre, 0.f) + log1pf(__expf(-fabsf(dpre)));
            float bk = (ACCF(3 * cc + 2, j) + bbb) * (1.f + alp * p);
            av[j]  = __expf(delta * Ac);
            bxv[j] = delta * bk * xp;
        }
        size_t o = outbase + (size_t)c * PLANE;
        union { uint4 u; __half2 h[4]; } pa, pb;
        pa.h[0] = __floats2half2_rn(av[0], av[1]);
        pa.h[1] = __floats2half2_rn(av[2], av[3]);
        pa.h[2] = __floats2half2_rn(av[4], av[5]);
        pa.h[3] = __floats2half2_rn(av[6], av[7]);
        pb.h[0] = __floats2half2_rn(bxv[0], bxv[1]);
        pb.h[1] = __floats2half2_rn(bxv[2], bxv[3]);
        pb.h[2] = __floats2half2_rn(bxv[4], bxv[5]);
        pb.h[3] = __floats2half2_rn(bxv[6], bxv[7]);
        *(uint4*)&g_Abar[o] = pa.u;
        *(uint4*)&g_bx[o]   = pb.u;
    }
    #undef ACCF
}

// ============================================================
// K_scanH: block per (b,c) plane, 512 thr = 128 col-pairs x 4 row-chunks.
// Two-pass affine chunked scan (pass2 re-reads from L1/L2).
// ============================================================
__global__ __launch_bounds__(512) void kscanH()
{
    __shared__ float2 AcS[512], BcS[512], hinS[512];
    int tid = threadIdx.x;
    int cp = tid & 127;          // column pair (2 cols via half2)
    int ch = tid >> 7;           // row chunk (64 rows)
    size_t base = (size_t)blockIdx.x * PLANE + (size_t)ch * (64 * 256) + cp * 2;
    const __half2* A2 = (const __half2*)g_Abar;
    const __half2* B2 = (const __half2*)g_bx;
    size_t h2 = base >> 1;       // half2 index; row stride = 128 half2

    float2 Ac = make_float2(1.f, 1.f), Bc = make_float2(0.f, 0.f);
    #pragma unroll 8
    for (int r = 0; r < 64; r++) {
        float2 a = __half22float2(A2[h2 + (size_t)r * 128]);
        float2 b = __half22float2(B2[h2 + (size_t)r * 128]);
        Bc.x = fmaf(a.x, Bc.x, b.x); Bc.y = fmaf(a.y, Bc.y, b.y);
        Ac.x *= a.x; Ac.y *= a.y;
    }
    AcS[tid] = Ac; BcS[tid] = Bc;
    __syncthreads();
    if (tid < 128) {
        float2 h = make_float2(0.f, 0.f);
        #pragma unroll
        for (int c = 0; c < 4; c++) {
            hinS[c * 128 + tid] = h;
            float2 A = AcS[c * 128 + tid];
            float2 B = BcS[c * 128 + tid];
            h.x = fmaf(A.x, h.x, B.x); h.y = fmaf(A.y, h.y, B.y);
        }
    }
    __syncthreads();
    float2 h = hinS[tid];
    __half2* S2 = (__half2*)g_sH;
    #pragma unroll 8
    for (int r = 0; r < 64; r++) {
        float2 a = __half22float2(A2[h2 + (size_t)r * 128]);
        float2 b = __half22float2(B2[h2 + (size_t)r * 128]);
        h.x = fmaf(a.x, h.x, b.x); h.y = fmaf(a.y, h.y, b.y);
        S2[h2 + (size_t)r * 128] = __floats2half2_rn(h.x, h.y);
    }
}

// ============================================================
// K_scanW: warp per row; affine Kogge-Stone scan, uint4 (8 half) per lane.
// Fused: writes g_s = sH + sW.
// ============================================================
__device__ __forceinline__ void unpack8h(uint4 u, float* f) {
    float2 t;
    t = __half22float2(*(__half2*)&u.x); f[0] = t.x; f[1] = t.y;
    t = __half22float2(*(__half2*)&u.y); f[2] = t.x; f[3] = t.y;
    t = __half22float2(*(__half2*)&u.z); f[4] = t.x; f[5] = t.y;
    t = __half22float2(*(__half2*)&u.w); f[6] = t.x; f[7] = t.y;
}

__global__ __launch_bounds__(256) void kscanW()
{
    int warp = threadIdx.x >> 5;
    int lane = threadIdx.x & 31;
    size_t row = (size_t)blockIdx.x * 8 + warp;        // 0..131071
    size_t base = row * 256 + lane * 8;                // half index

    uint4 ua = *(const uint4*)(g_Abar + base);
    uint4 ub = *(const uint4*)(g_bx + base);
    float a[8], b[8];
    unpack8h(ua, a); unpack8h(ub, b);

    float Ac = 1.f, Bc = 0.f;
    #pragma unroll
    for (int i = 0; i < 8; i++) {
        Bc = fmaf(a[i], Bc, b[i]);
        Ac = a[i] * Ac;
    }
    #pragma unroll
    for (int d = 1; d < 32; d <<= 1) {
        float Ap = __shfl_up_sync(0xffffffffu, Ac, d);
        float Bp = __shfl_up_sync(0xffffffffu, Bc, d);
        if (lane >= d) {
            Bc = fmaf(Ac, Bp, Bc);
            Ac = Ac * Ap;
        }
    }
    float hin = __shfl_up_sync(0xffffffffu, Bc, 1);
    if (lane == 0) hin = 0.f;

    uint4 us = *(const uint4*)(g_sH + base);
    float s[8];
    unpack8h(us, s);

    float h = hin, r[8];
    #pragma unroll
    for (int i = 0; i < 8; i++) {
        h = fmaf(a[i], h, b[i]);
        r[i] = h + s[i];
    }
    union { uint4 u; __half2 hh[4]; } o;
    o.hh[0] = __floats2half2_rn(r[0], r[1]);
    o.hh[1] = __floats2half2_rn(r[2], r[3]);
    o.hh[2] = __floats2half2_rn(r[4], r[5]);
    o.hh[3] = __floats2half2_rn(r[6], r[7]);
    *(uint4*)(g_s + base) = o.u;
}

// ============================================================
// K_out: out = x + gamma * (W_out @ s + b_out) ; f32x2 GEMM M=64,K=128
// ============================================================
#define SMEM_OUT ((128 * 64 + 128 * 64) * 4)

__global__ __launch_bounds__(256) void kout(
    const float* __restrict__ x,
    const float* __restrict__ W_out,
    const float* __restrict__ b_out,
    const float* __restrict__ gam_p,
    float* __restrict__ out)
{
    extern __shared__ float smem[];
    float* wo = smem;                // [k][64] m-contiguous
    float* xsum = smem + 128 * 64;   // [k][64]

    int tid = threadIdx.x;
    int pix0 = blockIdx.x * 64;
    int bi = pix0 >> 16;
    int hw0 = pix0 & 65535;

    for (int q = tid; q < 2048; q += 256) {
        int m = q & 63, kc = q >> 6;
        float4 w = *(const float4*)&W_out[m * 128 + kc * 4];
        wo[(kc * 4 + 0) * 64 + m] = w.x;
        wo[(kc * 4 + 1) * 64 + m] = w.y;
        wo[(kc * 4 + 2) * 64 + m] = w.z;
        wo[(kc * 4 + 3) * 64 + m] = w.w;
    }
    size_t sb = (size_t)bi * HID * PLANE + hw0;
    for (int q = tid; q < 128 * 32; q += 256) {
        int c = q >> 5, p = (q & 31) * 2;
        float2 v = __half22float2(*(const __half2*)&g_s[sb + (size_t)c * PLANE + p]);
        *(float2*)&xsum[c * 64 + p] = v;
    }
    __syncthreads();

    int tc = tid & 15;    // px group tc*4
    int tr = tid >> 4;    // row group tr*4 (2 row-pairs)

    ull acc[2][4];
    #pragma unroll
    for (int i = 0; i < 2; i++)
        #pragma unroll
        for (int j = 0; j < 4; j++) acc[i][j] = 0ULL;

    const float* wk = wo + tr * 4;
    const float* xk = xsum + tc * 4;
    #pragma unroll 8
    for (int k = 0; k < 128; k++) {
        F4U w, xv;
        w.f  = *(const float4*)(wk + k * 64);
        xv.f = *(const float4*)(xk + k * 64);
        ull xd[4];
        xd[0] = pk2(xv.f.x, xv.f.x); xd[1] = pk2(xv.f.y, xv.f.y);
        xd[2] = pk2(xv.f.z, xv.f.z); xd[3] = pk2(xv.f.w, xv.f.w);
        #pragma unroll
        for (int j = 0; j < 4; j++) {
            acc[0][j] = fma2(w.u[0], xd[j], acc[0][j]);
            acc[1][j] = fma2(w.u[1], xd[j], acc[1][j]);
        }
    }

    float gam = *gam_p;
    #pragma unroll
    for (int i = 0; i < 4; i++) {
        int co = tr * 4 + i;
        float bo = b_out[co];
        float v0 = (i & 1) ? upk(acc[i >> 1][0]).y : upk(acc[i >> 1][0]).x;
        float v1 = (i & 1) ? upk(acc[i >> 1][1]).y : upk(acc[i >> 1][1]).x;
        float v2 = (i & 1) ? upk(acc[i >> 1][2]).y : upk(acc[i >> 1][2]).x;
        float v3 = (i & 1) ? upk(acc[i >> 1][3]).y : upk(acc[i >> 1][3]).x;
        size_t base = (size_t)bi * CIN * PLANE + (size_t)co * PLANE + hw0 + tc * 4;
        float4 xg = *(const float4*)&x[base];
        float4 o;
        o.x = fmaf(gam, v0 + bo, xg.x);
        o.y = fmaf(gam, v1 + bo, xg.y);
        o.z = fmaf(gam, v2 + bo, xg.z);
        o.w = fmaf(gam, v3 + bo, xg.w);
        *(float4*)&out[base] = o;
    }
}

// ============================================================
extern "C" void kernel_launch(void* const* d_in, const int* in_sizes, int n_in,
                              void* d_out, int out_size)
{
    const float* x       = (const float*)d_in[0];
    const float* prior   = (const float*)d_in[1];
    const float* W_in    = (const float*)d_in[2];
    const float* b_in    = (const float*)d_in[3];
    const float* W_out   = (const float*)d_in[4];
    const float* b_out   = (const float*)d_in[5];
    const float* W_delta = (const float*)d_in[6];
    const float* b_delta = (const float*)d_in[7];
    const float* W_B     = (const float*)d_in[8];
    const float* b_B     = (const float*)d_in[9];
    const float* A_param = (const float*)d_in[10];
    const float* lam     = (const float*)d_in[11];
    const float* alp     = (const float*)d_in[12];
    const float* gam     = (const float*)d_in[13];
    float* out = (float*)d_out;

    cudaFuncSetAttribute(kproj, cudaFuncAttributeMaxDynamicSharedMemorySize, SMEM_PROJ);
    cudaFuncSetAttribute(kout, cudaFuncAttributeMaxDynamicSharedMemorySize, SMEM_OUT);

    kpre<<<99, 256>>>(W_in, b_in, W_delta, b_delta, W_B, b_B, A_param);
    kprior<<<NPIX / 256, 256>>>(prior, out + OUT2);
    kproj<<<NPIX / 64, 256, SMEM_PROJ>>>(x, lam, alp);
    kscanH<<<BATCH * HID, 512>>>();
    kscanW<<<(BATCH * HID * 256) / 8, 256>>>();
    kout<<<NPIX / 64, 256, SMEM_OUT>>>(x, W_out, b_out, gam, out);
}

// round 5
// speedup vs baseline: 1.8403x; 1.7392x over previous
#include <cuda_runtime.h>
#include <cuda_fp16.h>

#define BATCH 4
#define CIN   64
#define HID   128
#define PLANE 65536          // 256*256
#define NPIX  262144         // BATCH*PLANE
#define NELEM 33554432       // BATCH*HID*PLANE
#define OUT2  16777216       // BATCH*CIN*PLANE  (offset of prior_up in d_out)

// -------- scratch (static device globals: no allocation allowed) --------
__device__ float  g_ball[384];        // combined biases, index 3c+role
__device__ float  g_Aconst[HID];      // -exp(A_param)
__device__ float  g_prior[NPIX];      // clipped upsampled prior
__device__ __align__(16) __half g_Wh[64 * 384];  // fp16 combined weights [k][n], n=role*128+c, XOR-swizzled
__device__ __half g_Abar[NELEM];
__device__ __half g_bx[NELEM];
__device__ __half g_sH[NELEM];        // H-scan result
__device__ __half g_s[NELEM];         // sH + sW (fused in kscanW)

__device__ __forceinline__ unsigned s2u(const void* p) {
    return (unsigned)__cvta_generic_to_shared(p);
}
__device__ __forceinline__ void ldsm_x4(unsigned* r, unsigned addr) {
    asm volatile("ldmatrix.sync.aligned.m8n8.x4.shared.b16 {%0,%1,%2,%3}, [%4];"
                 : "=r"(r[0]), "=r"(r[1]), "=r"(r[2]), "=r"(r[3]) : "r"(addr));
}
__device__ __forceinline__ void ldsm_x2t(unsigned* r, unsigned addr) {
    asm volatile("ldmatrix.sync.aligned.m8n8.x2.trans.shared.b16 {%0,%1}, [%2];"
                 : "=r"(r[0]), "=r"(r[1]) : "r"(addr));
}
__device__ __forceinline__ void mma16816(float* d, const unsigned* a, const unsigned* b) {
    asm volatile("mma.sync.aligned.m16n8k16.row.col.f32.f16.f16.f32 "
                 "{%0,%1,%2,%3},{%4,%5,%6,%7},{%8,%9},{%0,%1,%2,%3};"
                 : "+f"(d[0]), "+f"(d[1]), "+f"(d[2]), "+f"(d[3])
                 : "r"(a[0]), "r"(a[1]), "r"(a[2]), "r"(a[3]), "r"(b[0]), "r"(b[1]));
}

// ============================================================
// K_pre: combined fp16 weights  (role 0: W_in, 1: W_delta@W_in, 2: W_B@W_in)
// stored [k][n=role*128+c] with 8-half XOR swizzle; biases; A_const
// ============================================================
__global__ __launch_bounds__(256) void kpre(
    const float* __restrict__ W_in, const float* __restrict__ b_in,
    const float* __restrict__ W_delta, const float* __restrict__ b_delta,
    const float* __restrict__ W_B, const float* __restrict__ b_B,
    const float* __restrict__ A_param)
{
    int idx = blockIdx.x * 256 + threadIdx.x;
    if (idx < 384 * 64) {
        int r = idx >> 6, k = idx & 63;
        int c = r / 3, q = r - 3 * c;
        float v;
        if (q == 0) {
            v = W_in[c * 64 + k];
        } else {
            const float* Wm = (q == 1) ? W_delta : W_B;
            float s = 0.f;
            #pragma unroll 4
            for (int j = 0; j < 128; j++) s = fmaf(Wm[c * 128 + j], W_in[j * 64 + k], s);
            v = s;
        }
        int n = q * 128 + c;
        g_Wh[k * 384 + (((n >> 3) ^ (k & 7)) << 3) + (n & 7)] = __float2half(v);
    } else if (idx < 384 * 64 + 384) {
        int r = idx - 384 * 64;
        int c = r / 3, q = r - 3 * c;
        float v;
        if (q == 0) {
            v = b_in[c];
        } else {
            const float* Wm = (q == 1) ? W_delta : W_B;
            const float* bm = (q == 1) ? b_delta : b_B;
            float s = bm[c];
            #pragma unroll 4
            for (int j = 0; j < 128; j++) s = fmaf(Wm[c * 128 + j], b_in[j], s);
            v = s;
        }
        g_ball[r] = v;
    } else if (idx < 384 * 64 + 384 + HID) {
        int c = idx - (384 * 64 + 384);
        g_Aconst[c] = -expf(A_param[c]);
    }
}

// ============================================================
// K_prior: bilinear (align_corners) 64x64 -> 256x256, clip [-1,1]
// ============================================================
__global__ __launch_bounds__(256) void kprior(
    const float* __restrict__ prior, float* __restrict__ out2)
{
    int tid = blockIdx.x * 256 + threadIdx.x;
    int bi = tid >> 16;
    int hw = tid & 65535;
    int oy = hw >> 8, ox = hw & 255;

    float fy = (float)(oy * 63) / 255.0f;
    float fx = (float)(ox * 63) / 255.0f;
    int y0 = (int)fy; int y1 = min(y0 + 1, 63);
    int x0 = (int)fx; int x1 = min(x0 + 1, 63);
    float wy = fy - (float)y0;
    float wx = fx - (float)x0;

    const float* p = prior + bi * 4096;
    float v00 = p[y0 * 64 + x0], v10 = p[y1 * 64 + x0];
    float v01 = p[y0 * 64 + x1], v11 = p[y1 * 64 + x1];
    float r0 = v00 * (1.f - wy) + v10 * wy;
    float r1 = v01 * (1.f - wy) + v11 * wy;
    float val = r0 * (1.f - wx) + r1 * wx;
    val = fminf(fmaxf(val, -1.f), 1.f);

    g_prior[tid] = val;
    out2[tid] = val;
}

// ============================================================
// K_proj: fp16 tensor-core GEMM  D[px=64, n=384] = Xt[64,64] @ Wh[64,384]
// + fused epilogue -> A_bar (fp16), bx (fp16). 512 threads / 16 warps,
// warp tile = 4 m-atoms x 3 n-atoms (one per role).
// ============================================================
// smem (halfs): Wh 24576 | Xt 4096 | (floats) ps 64, ball 384, Ac 128
#define SMEM_KP (57344 + 2304)

__global__ __launch_bounds__(512) void kproj(
    const float* __restrict__ x,
    const float* __restrict__ lam_p,
    const float* __restrict__ alp_p)
{
    extern __shared__ __half sm[];
    __half* sWh = sm;
    __half* sXt = sm + 24576;
    float* fb   = (float*)(sm + 28672);
    float* ps    = fb;          // [64]
    float* sball = fb + 64;     // [384]
    float* sAc   = fb + 448;    // [128]

    int tid = threadIdx.x;
    int pix0 = blockIdx.x * 64;
    int bi = pix0 >> 16;
    int hw0 = pix0 & 65535;

    // fill Wh (already swizzled in global)
    {
        const uint4* gW = (const uint4*)g_Wh;
        uint4* sW = (uint4*)sWh;
        #pragma unroll
        for (int q = tid; q < 3072; q += 512) sW[q] = gW[q];
    }
    // fill Xt transposed + swizzled: Xt[p][c]
    {
        const float* xg = x + (size_t)bi * CIN * PLANE + hw0;
        #pragma unroll
        for (int q = tid; q < 4096; q += 512) {
            int c = q >> 6, p = q & 63;
            float v = xg[(size_t)c * PLANE + p];
            sXt[(p << 6) + (((c >> 3) ^ (p & 7)) << 3) + (c & 7)] = __float2half(v);
        }
    }
    // constant staging (overlapping predicates so ALL entries load with 512 thr)
    if (tid < 64) ps[tid] = g_prior[pix0 + tid];
    if (tid >= 64 && tid < 448) sball[tid - 64] = g_ball[tid - 64];
    if (tid >= 384) sAc[tid - 384] = g_Aconst[tid - 384];   // tid 384..511 -> 128 entries
    __syncthreads();

    int w = tid >> 5, lane = tid & 31;
    int wp = w & 7, jw = w >> 3;
    int lr = lane & 15;       // row 0..15 within 16
    int lh = lane >> 4;       // 0/1: col-half

    float acc[4][3][4];
    #pragma unroll
    for (int i = 0; i < 4; i++)
        #pragma unroll
        for (int j = 0; j < 3; j++)
            #pragma unroll
            for (int q = 0; q < 4; q++) acc[i][j][q] = 0.f;

    #pragma unroll
    for (int kc = 0; kc < 4; kc++) {
        unsigned a[4][4];
        #pragma unroll
        for (int ma = 0; ma < 4; ma++) {
            int row = ma * 16 + lr;
            int colb = kc * 16 + lh * 8;
            unsigned addr = s2u(&sXt[(row << 6) + (((colb >> 3) ^ (row & 7)) << 3)]);
            ldsm_x4(a[ma], addr);
        }
        unsigned b[3][2];
        #pragma unroll
        for (int r3 = 0; r3 < 3; r3++) {
            int na = r3 * 16 + wp * 2 + jw;
            int k = kc * 16 + lr;
            int nb = na * 8;
            unsigned addr = s2u(&sWh[k * 384 + (((nb >> 3) ^ (k & 7)) << 3)]);
            ldsm_x2t(b[r3], addr);
        }
        #pragma unroll
        for (int ma = 0; ma < 4; ma++)
            #pragma unroll
            for (int r3 = 0; r3 < 3; r3++)
                mma16816(acc[ma][r3], a[ma], b[r3]);
    }
    __syncthreads();   // done with sWh/sXt -> reuse for staging

    __half* sA = sm;            // [128][72]
    __half* sB = sm + 9216;     // [128][72]
    float lam = *lam_p;
    float alp = *alp_p;

    #pragma unroll
    for (int i = 0; i < 2; i++) {
        int c = wp * 16 + jw * 8 + (lane & 3) * 2 + i;
        float bin = sball[3 * c];
        float bdl = sball[3 * c + 1];
        float bbb = sball[3 * c + 2];
        float Ac  = sAc[c];
        #pragma unroll
        for (int ma = 0; ma < 4; ma++) {
            #pragma unroll
            for (int rr = 0; rr < 2; rr++) {
                int px = ma * 16 + (lane >> 2) + rr * 8;
                int idx = rr * 2 + i;
                float p = ps[px];
                float xp   = acc[ma][0][idx] + bin;
                float dpre = acc[ma][1][idx] + bdl + lam * p;
                float delta = fmaxf(dpre, 0.f) + log1pf(__expf(-fabsf(dpre)));
                float bk = (acc[ma][2][idx] + bbb) * (1.f + alp * p);
                sA[c * 72 + px] = __float2half(__expf(delta * Ac));
                sB[c * 72 + px] = __float2half(delta * bk * xp);
            }
        }
    }
    __syncthreads();

    // coalesced output: 128 ch x 64 px, uint4 (8 halfs) per store
    size_t ob = (size_t)bi * HID * PLANE + hw0;
    #pragma unroll
    for (int q = tid; q < 1024; q += 512) {
        int c = q >> 3, p8 = (q & 7) * 8;
        *(uint4*)&g_Abar[ob + (size_t)c * PLANE + p8] = *(const uint4*)&sA[c * 72 + p8];
        *(uint4*)&g_bx[ob + (size_t)c * PLANE + p8]   = *(const uint4*)&sB[c * 72 + p8];
    }
}

// ============================================================
// K_scanH: block per (b,c) plane, 512 thr = 128 col-pairs x 4 row-chunks.
// ============================================================
__global__ __launch_bounds__(512) void kscanH()
{
    __shared__ float2 AcS[512], BcS[512], hinS[512];
    int tid = threadIdx.x;
    int cp = tid & 127;
    int ch = tid >> 7;
    size_t base = (size_t)blockIdx.x * PLANE + (size_t)ch * (64 * 256) + cp * 2;
    const __half2* A2 = (const __half2*)g_Abar;
    const __half2* B2 = (const __half2*)g_bx;
    size_t h2 = base >> 1;

    float2 Ac = make_float2(1.f, 1.f), Bc = make_float2(0.f, 0.f);
    #pragma unroll 8
    for (int r = 0; r < 64; r++) {
        float2 a = __half22float2(A2[h2 + (size_t)r * 128]);
        float2 b = __half22float2(B2[h2 + (size_t)r * 128]);
        Bc.x = fmaf(a.x, Bc.x, b.x); Bc.y = fmaf(a.y, Bc.y, b.y);
        Ac.x *= a.x; Ac.y *= a.y;
    }
    AcS[tid] = Ac; BcS[tid] = Bc;
    __syncthreads();
    if (tid < 128) {
        float2 h = make_float2(0.f, 0.f);
        #pragma unroll
        for (int c = 0; c < 4; c++) {
            hinS[c * 128 + tid] = h;
            float2 A = AcS[c * 128 + tid];
            float2 B = BcS[c * 128 + tid];
            h.x = fmaf(A.x, h.x, B.x); h.y = fmaf(A.y, h.y, B.y);
        }
    }
    __syncthreads();
    float2 h = hinS[tid];
    __half2* S2 = (__half2*)g_sH;
    #pragma unroll 8
    for (int r = 0; r < 64; r++) {
        float2 a = __half22float2(A2[h2 + (size_t)r * 128]);
        float2 b = __half22float2(B2[h2 + (size_t)r * 128]);
        h.x = fmaf(a.x, h.x, b.x); h.y = fmaf(a.y, h.y, b.y);
        S2[h2 + (size_t)r * 128] = __floats2half2_rn(h.x, h.y);
    }
}

// ============================================================
// K_scanW: warp per row; affine Kogge-Stone, uint4 (8 half) per lane.
// Fused: writes g_s = sH + sW.
// ============================================================
__device__ __forceinline__ void unpack8h(uint4 u, float* f) {
    float2 t;
    t = __half22float2(*(__half2*)&u.x); f[0] = t.x; f[1] = t.y;
    t = __half22float2(*(__half2*)&u.y); f[2] = t.x; f[3] = t.y;
    t = __half22float2(*(__half2*)&u.z); f[4] = t.x; f[5] = t.y;
    t = __half22float2(*(__half2*)&u.w); f[6] = t.x; f[7] = t.y;
}

__global__ __launch_bounds__(256) void kscanW()
{
    int warp = threadIdx.x >> 5;
    int lane = threadIdx.x & 31;
    size_t row = (size_t)blockIdx.x * 8 + warp;
    size_t base = row * 256 + lane * 8;

    uint4 ua = *(const uint4*)(g_Abar + base);
    uint4 ub = *(const uint4*)(g_bx + base);
    float a[8], b[8];
    unpack8h(ua, a); unpack8h(ub, b);

    float Ac = 1.f, Bc = 0.f;
    #pragma unroll
    for (int i = 0; i < 8; i++) {
        Bc = fmaf(a[i], Bc, b[i]);
        Ac = a[i] * Ac;
    }
    #pragma unroll
    for (int d = 1; d < 32; d <<= 1) {
        float Ap = __shfl_up_sync(0xffffffffu, Ac, d);
        float Bp = __shfl_up_sync(0xffffffffu, Bc, d);
        if (lane >= d) {
            Bc = fmaf(Ac, Bp, Bc);
            Ac = Ac * Ap;
        }
    }
    float hin = __shfl_up_sync(0xffffffffu, Bc, 1);
    if (lane == 0) hin = 0.f;

    uint4 us = *(const uint4*)(g_sH + base);
    float s[8];
    unpack8h(us, s);

    float h = hin, r[8];
    #pragma unroll
    for (int i = 0; i < 8; i++) {
        h = fmaf(a[i], h, b[i]);
        r[i] = h + s[i];
    }
    union { uint4 u; __half2 hh[4]; } o;
    o.hh[0] = __floats2half2_rn(r[0], r[1]);
    o.hh[1] = __floats2half2_rn(r[2], r[3]);
    o.hh[2] = __floats2half2_rn(r[4], r[5]);
    o.hh[3] = __floats2half2_rn(r[6], r[7]);
    *(uint4*)(g_s + base) = o.u;
}

// ============================================================
// K_out: out = x + gamma * (W_out @ s + b_out) ; FFMA GEMM M=64,K=128
// ============================================================
#define SMEM_OUT ((128 * 64 + 128 * 64) * 4)

__global__ __launch_bounds__(256) void kout(
    const float* __restrict__ x,
    const float* __restrict__ W_out,
    const float* __restrict__ b_out,
    const float* __restrict__ gam_p,
    float* __restrict__ out)
{
    extern __shared__ float smem[];
    float* wo = smem;                // [k][64] m-contiguous
    float* xsum = smem + 128 * 64;   // [k][64]

    int tid = threadIdx.x;
    int pix0 = blockIdx.x * 64;
    int bi = pix0 >> 16;
    int hw0 = pix0 & 65535;

    for (int q = tid; q < 2048; q += 256) {
        int m = q & 63, kc = q >> 6;
        float4 w = *(const float4*)&W_out[m * 128 + kc * 4];
        wo[(kc * 4 + 0) * 64 + m] = w.x;
        wo[(kc * 4 + 1) * 64 + m] = w.y;
        wo[(kc * 4 + 2) * 64 + m] = w.z;
        wo[(kc * 4 + 3) * 64 + m] = w.w;
    }
    size_t sb = (size_t)bi * HID * PLANE + hw0;
    for (int q = tid; q < 128 * 32; q += 256) {
        int c = q >> 5, p = (q & 31) * 2;
        float2 v = __half22float2(*(const __half2*)&g_s[sb + (size_t)c * PLANE + p]);
        *(float2*)&xsum[c * 64 + p] = v;
    }
    __syncthreads();

    int tc = tid & 15;    // px group tc*4
    int tr = tid >> 4;    // row group tr*4

    float acc[4][4];
    #pragma unroll
    for (int i = 0; i < 4; i++)
        #pragma unroll
        for (int j = 0; j < 4; j++) acc[i][j] = 0.f;

    const float* wk = wo + tr * 4;
    const float* xk = xsum + tc * 4;
    #pragma unroll 8
    for (int k = 0; k < 128; k++) {
        float4 w = *(const float4*)(wk + k * 64);
        float4 xv = *(const float4*)(xk + k * 64);
        float wv[4] = {w.x, w.y, w.z, w.w};
        float xx[4] = {xv.x, xv.y, xv.z, xv.w};
        #pragma unroll
        for (int i = 0; i < 4; i++)
            #pragma unroll
            for (int j = 0; j < 4; j++)
                acc[i][j] = fmaf(wv[i], xx[j], acc[i][j]);
    }

    float gam = *gam_p;
    #pragma unroll
    for (int i = 0; i < 4; i++) {
        int co = tr * 4 + i;
        float bo = b_out[co];
        size_t base = (size_t)bi * CIN * PLANE + (size_t)co * PLANE + hw0 + tc * 4;
        float4 xg = *(const float4*)&x[base];
        float4 o;
        o.x = fmaf(gam, acc[i][0] + bo, xg.x);
        o.y = fmaf(gam, acc[i][1] + bo, xg.y);
        o.z = fmaf(gam, acc[i][2] + bo, xg.z);
        o.w = fmaf(gam, acc[i][3] + bo, xg.w);
        *(float4*)&out[base] = o;
    }
}

// ============================================================
extern "C" void kernel_launch(void* const* d_in, const int* in_sizes, int n_in,
                              void* d_out, int out_size)
{
    const float* x       = (const float*)d_in[0];
    const float* prior   = (const float*)d_in[1];
    const float* W_in    = (const float*)d_in[2];
    const float* b_in    = (const float*)d_in[3];
    const float* W_out   = (const float*)d_in[4];
    const float* b_out   = (const float*)d_in[5];
    const float* W_delta = (const float*)d_in[6];
    const float* b_delta = (const float*)d_in[7];
    const float* W_B     = (const float*)d_in[8];
    const float* b_B     = (const float*)d_in[9];
    const float* A_param = (const float*)d_in[10];
    const float* lam     = (const float*)d_in[11];
    const float* alp     = (const float*)d_in[12];
    const float* gam     = (const float*)d_in[13];
    float* out = (float*)d_out;

    cudaFuncSetAttribute(kproj, cudaFuncAttributeMaxDynamicSharedMemorySize, SMEM_KP);
    cudaFuncSetAttribute(kout, cudaFuncAttributeMaxDynamicSharedMemorySize, SMEM_OUT);

    kpre<<<99, 256>>>(W_in, b_in, W_delta, b_delta, W_B, b_B, A_param);
    kprior<<<NPIX / 256, 256>>>(prior, out + OUT2);
    kproj<<<NPIX / 64, 512, SMEM_KP>>>(x, lam, alp);
    kscanH<<<BATCH * HID, 512>>>();
    kscanW<<<(BATCH * HID * 256) / 8, 256>>>();
    kout<<<NPIX / 64, 256, SMEM_OUT>>>(x, W_out, b_out, gam, out);
}

// round 6
// speedup vs baseline: 3.0288x; 1.6458x over previous
#include <cuda_runtime.h>
#include <cuda_fp16.h>

#define BATCH 4
#define CIN   64
#define HID   128
#define PLANE 65536          // 256*256
#define NPIX  262144         // BATCH*PLANE
#define NELEM 33554432       // BATCH*HID*PLANE
#define OUT2  16777216       // BATCH*CIN*PLANE  (offset of prior_up in d_out)

// -------- scratch (static device globals: no allocation allowed) --------
__device__ float  g_ball[384];        // combined biases, index 3c+role
__device__ float  g_Aconst[HID];      // -exp(A_param)
__device__ float  g_prior[NPIX];      // clipped upsampled prior
__device__ __align__(16) __half g_Wh[64 * 384];   // fp16 proj weights [k][n], n=role*128+c, swizzled
__device__ __align__(16) __half g_Woh[128 * 64];  // fp16 W_out [k][co], swizzled
__device__ __half g_Abar[NELEM];
__device__ __half g_bx[NELEM];
__device__ __half g_sH[NELEM];        // H-scan result
__device__ __half g_s[NELEM];         // sH + sW (fused in kscanW)

__device__ __forceinline__ unsigned s2u(const void* p) {
    return (unsigned)__cvta_generic_to_shared(p);
}
__device__ __forceinline__ void ldsm_x4(unsigned* r, unsigned addr) {
    asm volatile("ldmatrix.sync.aligned.m8n8.x4.shared.b16 {%0,%1,%2,%3}, [%4];"
                 : "=r"(r[0]), "=r"(r[1]), "=r"(r[2]), "=r"(r[3]) : "r"(addr));
}
__device__ __forceinline__ void ldsm_x4t(unsigned* r, unsigned addr) {
    asm volatile("ldmatrix.sync.aligned.m8n8.x4.trans.shared.b16 {%0,%1,%2,%3}, [%4];"
                 : "=r"(r[0]), "=r"(r[1]), "=r"(r[2]), "=r"(r[3]) : "r"(addr));
}
__device__ __forceinline__ void ldsm_x2t(unsigned* r, unsigned addr) {
    asm volatile("ldmatrix.sync.aligned.m8n8.x2.trans.shared.b16 {%0,%1}, [%2];"
                 : "=r"(r[0]), "=r"(r[1]) : "r"(addr));
}
__device__ __forceinline__ void mma16816(float* d, const unsigned* a, const unsigned* b) {
    asm volatile("mma.sync.aligned.m16n8k16.row.col.f32.f16.f16.f32 "
                 "{%0,%1,%2,%3},{%4,%5,%6,%7},{%8,%9},{%0,%1,%2,%3};"
                 : "+f"(d[0]), "+f"(d[1]), "+f"(d[2]), "+f"(d[3])
                 : "r"(a[0]), "r"(a[1]), "r"(a[2]), "r"(a[3]), "r"(b[0]), "r"(b[1]));
}

// ============================================================
// K_pre: combined fp16 weights + biases + A_const + fp16 W_out
// ============================================================
__global__ __launch_bounds__(256) void kpre(
    const float* __restrict__ W_in, const float* __restrict__ b_in,
    const float* __restrict__ W_delta, const float* __restrict__ b_delta,
    const float* __restrict__ W_B, const float* __restrict__ b_B,
    const float* __restrict__ A_param, const float* __restrict__ W_out)
{
    int idx = blockIdx.x * 256 + threadIdx.x;
    if (idx < 384 * 64) {
        int r = idx >> 6, k = idx & 63;
        int c = r / 3, q = r - 3 * c;
        float v;
        if (q == 0) {
            v = W_in[c * 64 + k];
        } else {
            const float* Wm = (q == 1) ? W_delta : W_B;
            float s = 0.f;
            #pragma unroll 4
            for (int j = 0; j < 128; j++) s = fmaf(Wm[c * 128 + j], W_in[j * 64 + k], s);
            v = s;
        }
        int n = q * 128 + c;
        g_Wh[k * 384 + (((n >> 3) ^ (k & 7)) << 3) + (n & 7)] = __float2half(v);
    } else if (idx < 384 * 64 + 384) {
        int r = idx - 384 * 64;
        int c = r / 3, q = r - 3 * c;
        float v;
        if (q == 0) {
            v = b_in[c];
        } else {
            const float* Wm = (q == 1) ? W_delta : W_B;
            const float* bm = (q == 1) ? b_delta : b_B;
            float s = bm[c];
            #pragma unroll 4
            for (int j = 0; j < 128; j++) s = fmaf(Wm[c * 128 + j], b_in[j], s);
            v = s;
        }
        g_ball[r] = v;
    } else if (idx < 384 * 64 + 384 + HID) {
        int c = idx - (384 * 64 + 384);
        g_Aconst[c] = -expf(A_param[c]);
    } else if (idx < 384 * 64 + 384 + HID + 128 * 64) {
        int t = idx - (384 * 64 + 384 + HID);
        int k = t >> 6, co = t & 63;
        g_Woh[k * 64 + (((co >> 3) ^ (k & 7)) << 3) + (co & 7)] =
            __float2half(W_out[co * 128 + k]);
    }
}

// ============================================================
// K_prior: bilinear (align_corners) 64x64 -> 256x256, clip [-1,1]
// ============================================================
__global__ __launch_bounds__(256) void kprior(
    const float* __restrict__ prior, float* __restrict__ out2)
{
    int tid = blockIdx.x * 256 + threadIdx.x;
    int bi = tid >> 16;
    int hw = tid & 65535;
    int oy = hw >> 8, ox = hw & 255;

    float fy = (float)(oy * 63) / 255.0f;
    float fx = (float)(ox * 63) / 255.0f;
    int y0 = (int)fy; int y1 = min(y0 + 1, 63);
    int x0 = (int)fx; int x1 = min(x0 + 1, 63);
    float wy = fy - (float)y0;
    float wx = fx - (float)x0;

    const float* p = prior + bi * 4096;
    float v00 = p[y0 * 64 + x0], v10 = p[y1 * 64 + x0];
    float v01 = p[y0 * 64 + x1], v11 = p[y1 * 64 + x1];
    float r0 = v00 * (1.f - wy) + v10 * wy;
    float r1 = v01 * (1.f - wy) + v11 * wy;
    float val = r0 * (1.f - wx) + r1 * wx;
    val = fminf(fmaxf(val, -1.f), 1.f);

    g_prior[tid] = val;
    out2[tid] = val;
}

// ============================================================
// K_proj: fp16 mma GEMM D[px=64, n=384] = Xt[64,64] @ Wh[64,384] + epilogue
// ============================================================
#define SMEM_KP (57344 + 2304)

__global__ __launch_bounds__(512) void kproj(
    const float* __restrict__ x,
    const float* __restrict__ lam_p,
    const float* __restrict__ alp_p)
{
    extern __shared__ __half sm[];
    __half* sWh = sm;
    __half* sXt = sm + 24576;
    float* fb   = (float*)(sm + 28672);
    float* ps    = fb;          // [64]
    float* sball = fb + 64;     // [384]
    float* sAc   = fb + 448;    // [128]

    int tid = threadIdx.x;
    int pix0 = blockIdx.x * 64;
    int bi = pix0 >> 16;
    int hw0 = pix0 & 65535;

    {
        const uint4* gW = (const uint4*)g_Wh;
        uint4* sW = (uint4*)sWh;
        #pragma unroll
        for (int q = tid; q < 3072; q += 512) sW[q] = gW[q];
    }
    {
        const float* xg = x + (size_t)bi * CIN * PLANE + hw0;
        #pragma unroll
        for (int q = tid; q < 4096; q += 512) {
            int c = q >> 6, p = q & 63;
            float v = xg[(size_t)c * PLANE + p];
            sXt[(p << 6) + (((c >> 3) ^ (p & 7)) << 3) + (c & 7)] = __float2half(v);
        }
    }
    if (tid < 64) ps[tid] = g_prior[pix0 + tid];
    if (tid >= 64 && tid < 448) sball[tid - 64] = g_ball[tid - 64];
    if (tid >= 384) sAc[tid - 384] = g_Aconst[tid - 384];
    __syncthreads();

    int w = tid >> 5, lane = tid & 31;
    int wp = w & 7, jw = w >> 3;
    int lr = lane & 15;
    int lh = lane >> 4;

    float acc[4][3][4];
    #pragma unroll
    for (int i = 0; i < 4; i++)
        #pragma unroll
        for (int j = 0; j < 3; j++)
            #pragma unroll
            for (int q = 0; q < 4; q++) acc[i][j][q] = 0.f;

    #pragma unroll
    for (int kc = 0; kc < 4; kc++) {
        unsigned a[4][4];
        #pragma unroll
        for (int ma = 0; ma < 4; ma++) {
            int row = ma * 16 + lr;
            int colb = kc * 16 + lh * 8;
            unsigned addr = s2u(&sXt[(row << 6) + (((colb >> 3) ^ (row & 7)) << 3)]);
            ldsm_x4(a[ma], addr);
        }
        unsigned b[3][2];
        #pragma unroll
        for (int r3 = 0; r3 < 3; r3++) {
            int na = r3 * 16 + wp * 2 + jw;
            int k = kc * 16 + lr;
            int nb = na * 8;
            unsigned addr = s2u(&sWh[k * 384 + (((nb >> 3) ^ (k & 7)) << 3)]);
            ldsm_x2t(b[r3], addr);
        }
        #pragma unroll
        for (int ma = 0; ma < 4; ma++)
            #pragma unroll
            for (int r3 = 0; r3 < 3; r3++)
                mma16816(acc[ma][r3], a[ma], b[r3]);
    }
    __syncthreads();

    __half* sA = sm;            // [128][72]
    __half* sB = sm + 9216;     // [128][72]
    float lam = *lam_p;
    float alp = *alp_p;

    #pragma unroll
    for (int i = 0; i < 2; i++) {
        int c = wp * 16 + jw * 8 + (lane & 3) * 2 + i;
        float bin = sball[3 * c];
        float bdl = sball[3 * c + 1];
        float bbb = sball[3 * c + 2];
        float Ac  = sAc[c];
        #pragma unroll
        for (int ma = 0; ma < 4; ma++) {
            #pragma unroll
            for (int rr = 0; rr < 2; rr++) {
                int px = ma * 16 + (lane >> 2) + rr * 8;
                int idx = rr * 2 + i;
                float p = ps[px];
                float xp   = acc[ma][0][idx] + bin;
                float dpre = acc[ma][1][idx] + bdl + lam * p;
                float delta = fmaxf(dpre, 0.f) + log1pf(__expf(-fabsf(dpre)));
                float bk = (acc[ma][2][idx] + bbb) * (1.f + alp * p);
                sA[c * 72 + px] = __float2half(__expf(delta * Ac));
                sB[c * 72 + px] = __float2half(delta * bk * xp);
            }
        }
    }
    __syncthreads();

    size_t ob = (size_t)bi * HID * PLANE + hw0;
    #pragma unroll
    for (int q = tid; q < 1024; q += 512) {
        int c = q >> 3, p8 = (q & 7) * 8;
        *(uint4*)&g_Abar[ob + (size_t)c * PLANE + p8] = *(const uint4*)&sA[c * 72 + p8];
        *(uint4*)&g_bx[ob + (size_t)c * PLANE + p8]   = *(const uint4*)&sB[c * 72 + p8];
    }
}

// ============================================================
// K_scanH: block = 256 rows x 64-col strip of one plane. Single DRAM pass:
// load A,b into smem, chunked two-pass scan in smem, coalesced write.
// grid = 512 planes * 4 strips = 2048
// ============================================================
#define SMEM_SH (65536 + 4096)

__global__ __launch_bounds__(256) void kscanH()
{
    extern __shared__ __half2 sh2[];
    __half2* sA2 = sh2;              // [256][32] half2
    __half2* sB2 = sh2 + 8192;
    float2* AcS  = (float2*)(sh2 + 16384);   // [8][32]
    float2* BcS  = AcS + 256;

    int tid = threadIdx.x;
    int blk = blockIdx.x;
    size_t gbase = (size_t)(blk >> 2) * PLANE + (size_t)(blk & 3) * 64;  // half index
    size_t gb2 = gbase >> 1;                                            // half2 index

    // load 256 rows x 64 cols of A and b (uint4 = 8 halves)
    {
        const __half* gA = g_Abar + gbase;
        const __half* gB = g_bx + gbase;
        #pragma unroll
        for (int q = tid; q < 2048; q += 256) {
            int r = q >> 3, g = q & 7;
            *(uint4*)&sA2[r * 32 + g * 4] = *(const uint4*)&gA[(size_t)r * 256 + g * 8];
            *(uint4*)&sB2[r * 32 + g * 4] = *(const uint4*)&gB[(size_t)r * 256 + g * 8];
        }
    }
    __syncthreads();

    int col2 = tid & 31;
    int chunk = tid >> 5;
    int r0 = chunk * 32;

    // pass 1: chunk affine composite
    float2 Ac = make_float2(1.f, 1.f), Bc = make_float2(0.f, 0.f);
    #pragma unroll 8
    for (int r = 0; r < 32; r++) {
        float2 a = __half22float2(sA2[(r0 + r) * 32 + col2]);
        float2 b = __half22float2(sB2[(r0 + r) * 32 + col2]);
        Bc.x = fmaf(a.x, Bc.x, b.x); Bc.y = fmaf(a.y, Bc.y, b.y);
        Ac.x *= a.x; Ac.y *= a.y;
    }
    AcS[tid] = Ac; BcS[tid] = Bc;
    __syncthreads();

    // per-thread chunk-prefix (<=7 serial steps)
    float2 h = make_float2(0.f, 0.f);
    for (int k = 0; k < chunk; k++) {
        float2 A = AcS[k * 32 + col2];
        float2 B = BcS[k * 32 + col2];
        h.x = fmaf(A.x, h.x, B.x); h.y = fmaf(A.y, h.y, B.y);
    }

    // pass 2: scan from smem, write global
    __half2* S2 = (__half2*)g_sH;
    #pragma unroll 8
    for (int r = 0; r < 32; r++) {
        float2 a = __half22float2(sA2[(r0 + r) * 32 + col2]);
        float2 b = __half22float2(sB2[(r0 + r) * 32 + col2]);
        h.x = fmaf(a.x, h.x, b.x); h.y = fmaf(a.y, h.y, b.y);
        S2[gb2 + (size_t)(r0 + r) * 128 + col2] = __floats2half2_rn(h.x, h.y);
    }
}

// ============================================================
// K_scanW: warp per row; affine Kogge-Stone, uint4 (8 half) per lane.
// Fused: writes g_s = sH + sW.
// ============================================================
__device__ __forceinline__ void unpack8h(uint4 u, float* f) {
    float2 t;
    t = __half22float2(*(__half2*)&u.x); f[0] = t.x; f[1] = t.y;
    t = __half22float2(*(__half2*)&u.y); f[2] = t.x; f[3] = t.y;
    t = __half22float2(*(__half2*)&u.z); f[4] = t.x; f[5] = t.y;
    t = __half22float2(*(__half2*)&u.w); f[6] = t.x; f[7] = t.y;
}

__global__ __launch_bounds__(256) void kscanW()
{
    int warp = threadIdx.x >> 5;
    int lane = threadIdx.x & 31;
    size_t row = (size_t)blockIdx.x * 8 + warp;
    size_t base = row * 256 + lane * 8;

    uint4 ua = *(const uint4*)(g_Abar + base);
    uint4 ub = *(const uint4*)(g_bx + base);
    float a[8], b[8];
    unpack8h(ua, a); unpack8h(ub, b);

    float Ac = 1.f, Bc = 0.f;
    #pragma unroll
    for (int i = 0; i < 8; i++) {
        Bc = fmaf(a[i], Bc, b[i]);
        Ac = a[i] * Ac;
    }
    #pragma unroll
    for (int d = 1; d < 32; d <<= 1) {
        float Ap = __shfl_up_sync(0xffffffffu, Ac, d);
        float Bp = __shfl_up_sync(0xffffffffu, Bc, d);
        if (lane >= d) {
            Bc = fmaf(Ac, Bp, Bc);
            Ac = Ac * Ap;
        }
    }
    float hin = __shfl_up_sync(0xffffffffu, Bc, 1);
    if (lane == 0) hin = 0.f;

    uint4 us = *(const uint4*)(g_sH + base);
    float s[8];
    unpack8h(us, s);

    float h = hin, r[8];
    #pragma unroll
    for (int i = 0; i < 8; i++) {
        h = fmaf(a[i], h, b[i]);
        r[i] = h + s[i];
    }
    union { uint4 u; __half2 hh[4]; } o;
    o.hh[0] = __floats2half2_rn(r[0], r[1]);
    o.hh[1] = __floats2half2_rn(r[2], r[3]);
    o.hh[2] = __floats2half2_rn(r[4], r[5]);
    o.hh[3] = __floats2half2_rn(r[6], r[7]);
    *(uint4*)(g_s + base) = o.u;
}

// ============================================================
// K_out: fp16 mma GEMM  D[px=64, co=64] = S[px,128] @ Wo[128,64]
// out = x + gamma * (D + b_out).  A loaded via ldmatrix.trans from k-major.
// ============================================================
#define SMEM_OUT2 (33024)

__global__ __launch_bounds__(256) void kout(
    const float* __restrict__ x,
    const float* __restrict__ b_out,
    const float* __restrict__ gam_p,
    float* __restrict__ out)
{
    extern __shared__ __half sm[];
    __half* sS  = sm;           // [k=128][px=64] swizzled
    __half* sWo = sm + 8192;    // [k=128][co=64] swizzled
    float* sbo  = (float*)(sm + 16384);   // [64]

    int tid = threadIdx.x;
    int pix0 = blockIdx.x * 64;
    int bi = pix0 >> 16;
    int hw0 = pix0 & 65535;

    // load S tile: rows = channel (k), 64 px each, swizzled uint4
    size_t sb = (size_t)bi * HID * PLANE + hw0;
    #pragma unroll
    for (int q = tid; q < 1024; q += 256) {
        int c = q >> 3, g = q & 7;
        *(uint4*)&sS[c * 64 + ((g ^ (c & 7)) << 3)] =
            *(const uint4*)&g_s[sb + (size_t)c * PLANE + g * 8];
    }
    // Wo already swizzled in global
    {
        const uint4* gW = (const uint4*)g_Woh;
        uint4* sW = (uint4*)sWo;
        #pragma unroll
        for (int q = tid; q < 1024; q += 256) sW[q] = gW[q];
    }
    if (tid < 64) sbo[tid] = b_out[tid];
    __syncthreads();

    int w = tid >> 5, lane = tid & 31;
    int wp = w & 3;          // m-atom (px group of 16)
    int jw = w >> 2;         // n-half (co 0-31 / 32-63)
    int lr = lane & 15;
    int kr = lane & 7, sel = lane >> 3;

    float acc[4][4];
    #pragma unroll
    for (int j = 0; j < 4; j++)
        #pragma unroll
        for (int q = 0; q < 4; q++) acc[j][q] = 0.f;

    #pragma unroll
    for (int kc = 0; kc < 8; kc++) {
        // A (px x k) via trans from k-major sS
        unsigned a[4];
        {
            int krow = kc * 16 + ((sel >> 1) << 3) + kr;
            int mcol = wp * 16 + ((sel & 1) << 3);
            unsigned addr = s2u(&sS[krow * 64 + (((mcol >> 3) ^ (krow & 7)) << 3)]);
            ldsm_x4t(a, addr);
        }
        // B: 4 n-atoms for this warp
        unsigned b[4][2];
        #pragma unroll
        for (int jn = 0; jn < 4; jn++) {
            int na = jw * 4 + jn;
            int k = kc * 16 + lr;
            unsigned addr = s2u(&sWo[k * 64 + ((na ^ (k & 7)) << 3)]);
            ldsm_x2t(b[jn], addr);
        }
        #pragma unroll
        for (int jn = 0; jn < 4; jn++)
            mma16816(acc[jn], a, b[jn]);
    }
    __syncthreads();

    // stage D in smem [co][px] (stride 68 for 16B-aligned rows)
    float* sD = (float*)sm;
    {
        int px = wp * 16 + (lane >> 2);
        #pragma unroll
        for (int jn = 0; jn < 4; jn++) {
            int co = (jw * 4 + jn) * 8 + (lane & 3) * 2;
            sD[co * 68 + px]           = acc[jn][0];
            sD[(co + 1) * 68 + px]     = acc[jn][1];
            sD[co * 68 + px + 8]       = acc[jn][2];
            sD[(co + 1) * 68 + px + 8] = acc[jn][3];
        }
    }
    __syncthreads();

    float gam = *gam_p;
    #pragma unroll
    for (int q = tid; q < 1024; q += 256) {
        int co = q >> 4, p4 = (q & 15) * 4;
        float bo = sbo[co];
        size_t base = (size_t)bi * CIN * PLANE + (size_t)co * PLANE + hw0 + p4;
        float4 xg = *(const float4*)&x[base];
        float4 dv = *(const float4*)&sD[co * 68 + p4];
        float4 o;
        o.x = fmaf(gam, dv.x + bo, xg.x);
        o.y = fmaf(gam, dv.y + bo, xg.y);
        o.z = fmaf(gam, dv.z + bo, xg.z);
        o.w = fmaf(gam, dv.w + bo, xg.w);
        *(float4*)&out[base] = o;
    }
}

// ============================================================
extern "C" void kernel_launch(void* const* d_in, const int* in_sizes, int n_in,
                              void* d_out, int out_size)
{
    const float* x       = (const float*)d_in[0];
    const float* prior   = (const float*)d_in[1];
    const float* W_in    = (const float*)d_in[2];
    const float* b_in    = (const float*)d_in[3];
    const float* W_out   = (const float*)d_in[4];
    const float* b_out   = (const float*)d_in[5];
    const float* W_delta = (const float*)d_in[6];
    const float* b_delta = (const float*)d_in[7];
    const float* W_B     = (const float*)d_in[8];
    const float* b_B     = (const float*)d_in[9];
    const float* A_param = (const float*)d_in[10];
    const float* lam     = (const float*)d_in[11];
    const float* alp     = (const float*)d_in[12];
    const float* gam     = (const float*)d_in[13];
    float* out = (float*)d_out;

    cudaFuncSetAttribute(kproj, cudaFuncAttributeMaxDynamicSharedMemorySize, SMEM_KP);
    cudaFuncSetAttribute(kscanH, cudaFuncAttributeMaxDynamicSharedMemorySize, SMEM_SH);
    cudaFuncSetAttribute(kout, cudaFuncAttributeMaxDynamicSharedMemorySize, SMEM_OUT2);

    kpre<<<130, 256>>>(W_in, b_in, W_delta, b_delta, W_B, b_B, A_param, W_out);
    kprior<<<NPIX / 256, 256>>>(prior, out + OUT2);
    kproj<<<NPIX / 64, 512, SMEM_KP>>>(x, lam, alp);
    kscanH<<<2048, 256, SMEM_SH>>>();
    kscanW<<<(BATCH * HID * 256) / 8, 256>>>();
    kout<<<NPIX / 64, 256, SMEM_OUT2>>>(x, b_out, gam, out);
}

// round 7
// speedup vs baseline: 3.1210x; 1.0305x over previous
#include <cuda_runtime.h>
#include <cuda_fp16.h>

#define BATCH 4
#define CIN   64
#define HID   128
#define PLANE 65536          // 256*256
#define NPIX  262144         // BATCH*PLANE
#define NELEM 33554432       // BATCH*HID*PLANE
#define OUT2  16777216       // BATCH*CIN*PLANE  (offset of prior_up in d_out)

// -------- scratch (static device globals: no allocation allowed) --------
__device__ float  g_ball[384];        // combined biases, index 3c+role
__device__ float  g_Aconst[HID];      // -exp(A_param)
__device__ float  g_prior[NPIX];      // clipped upsampled prior
__device__ __align__(16) __half g_Wh[64 * 384];   // fp16 proj weights [k][n], n=role*128+c, swizzled
__device__ __align__(16) __half g_Woh[128 * 64];  // fp16 W_out [k][co], swizzled
__device__ __half g_Abar[NELEM];
__device__ __half g_bx[NELEM];
__device__ __half g_sH[NELEM];        // H-scan result

__device__ __forceinline__ unsigned s2u(const void* p) {
    return (unsigned)__cvta_generic_to_shared(p);
}
__device__ __forceinline__ void ldsm_x4(unsigned* r, unsigned addr) {
    asm volatile("ldmatrix.sync.aligned.m8n8.x4.shared.b16 {%0,%1,%2,%3}, [%4];"
                 : "=r"(r[0]), "=r"(r[1]), "=r"(r[2]), "=r"(r[3]) : "r"(addr));
}
__device__ __forceinline__ void ldsm_x4t(unsigned* r, unsigned addr) {
    asm volatile("ldmatrix.sync.aligned.m8n8.x4.trans.shared.b16 {%0,%1,%2,%3}, [%4];"
                 : "=r"(r[0]), "=r"(r[1]), "=r"(r[2]), "=r"(r[3]) : "r"(addr));
}
__device__ __forceinline__ void ldsm_x2t(unsigned* r, unsigned addr) {
    asm volatile("ldmatrix.sync.aligned.m8n8.x2.trans.shared.b16 {%0,%1}, [%2];"
                 : "=r"(r[0]), "=r"(r[1]) : "r"(addr));
}
__device__ __forceinline__ void mma16816(float* d, const unsigned* a, const unsigned* b) {
    asm volatile("mma.sync.aligned.m16n8k16.row.col.f32.f16.f16.f32 "
                 "{%0,%1,%2,%3},{%4,%5,%6,%7},{%8,%9},{%0,%1,%2,%3};"
                 : "+f"(d[0]), "+f"(d[1]), "+f"(d[2]), "+f"(d[3])
                 : "r"(a[0]), "r"(a[1]), "r"(a[2]), "r"(a[3]), "r"(b[0]), "r"(b[1]));
}

// ============================================================
// K_pre: combined fp16 weights + biases + A_const + fp16 W_out
// ============================================================
__global__ __launch_bounds__(256) void kpre(
    const float* __restrict__ W_in, const float* __restrict__ b_in,
    const float* __restrict__ W_delta, const float* __restrict__ b_delta,
    const float* __restrict__ W_B, const float* __restrict__ b_B,
    const float* __restrict__ A_param, const float* __restrict__ W_out)
{
    int idx = blockIdx.x * 256 + threadIdx.x;
    if (idx < 384 * 64) {
        int r = idx >> 6, k = idx & 63;
        int c = r / 3, q = r - 3 * c;
        float v;
        if (q == 0) {
            v = W_in[c * 64 + k];
        } else {
            const float* Wm = (q == 1) ? W_delta : W_B;
            float s = 0.f;
            #pragma unroll 4
            for (int j = 0; j < 128; j++) s = fmaf(Wm[c * 128 + j], W_in[j * 64 + k], s);
            v = s;
        }
        int n = q * 128 + c;
        g_Wh[k * 384 + (((n >> 3) ^ (k & 7)) << 3) + (n & 7)] = __float2half(v);
    } else if (idx < 384 * 64 + 384) {
        int r = idx - 384 * 64;
        int c = r / 3, q = r - 3 * c;
        float v;
        if (q == 0) {
            v = b_in[c];
        } else {
            const float* Wm = (q == 1) ? W_delta : W_B;
            const float* bm = (q == 1) ? b_delta : b_B;
            float s = bm[c];
            #pragma unroll 4
            for (int j = 0; j < 128; j++) s = fmaf(Wm[c * 128 + j], b_in[j], s);
            v = s;
        }
        g_ball[r] = v;
    } else if (idx < 384 * 64 + 384 + HID) {
        int c = idx - (384 * 64 + 384);
        g_Aconst[c] = -expf(A_param[c]);
    } else if (idx < 384 * 64 + 384 + HID + 128 * 64) {
        int t = idx - (384 * 64 + 384 + HID);
        int k = t >> 6, co = t & 63;
        g_Woh[k * 64 + (((co >> 3) ^ (k & 7)) << 3) + (co & 7)] =
            __float2half(W_out[co * 128 + k]);
    }
}

// ============================================================
// K_prior: bilinear (align_corners) 64x64 -> 256x256, clip [-1,1]
// ============================================================
__global__ __launch_bounds__(256) void kprior(
    const float* __restrict__ prior, float* __restrict__ out2)
{
    int tid = blockIdx.x * 256 + threadIdx.x;
    int bi = tid >> 16;
    int hw = tid & 65535;
    int oy = hw >> 8, ox = hw & 255;

    float fy = (float)(oy * 63) / 255.0f;
    float fx = (float)(ox * 63) / 255.0f;
    int y0 = (int)fy; int y1 = min(y0 + 1, 63);
    int x0 = (int)fx; int x1 = min(x0 + 1, 63);
    float wy = fy - (float)y0;
    float wx = fx - (float)x0;

    const float* p = prior + bi * 4096;
    float v00 = p[y0 * 64 + x0], v10 = p[y1 * 64 + x0];
    float v01 = p[y0 * 64 + x1], v11 = p[y1 * 64 + x1];
    float r0 = v00 * (1.f - wy) + v10 * wy;
    float r1 = v01 * (1.f - wy) + v11 * wy;
    float val = r0 * (1.f - wx) + r1 * wx;
    val = fminf(fmaxf(val, -1.f), 1.f);

    g_prior[tid] = val;
    out2[tid] = val;
}

// ============================================================
// K_proj: fp16 mma GEMM D[px=64, n=384] = Xt[64,64] @ Wh[64,384] + epilogue
// ============================================================
#define SMEM_KP (57344 + 2304)

__global__ __launch_bounds__(512) void kproj(
    const float* __restrict__ x,
    const float* __restrict__ lam_p,
    const float* __restrict__ alp_p)
{
    extern __shared__ __half sm[];
    __half* sWh = sm;
    __half* sXt = sm + 24576;
    float* fb   = (float*)(sm + 28672);
    float* ps    = fb;          // [64]
    float* sball = fb + 64;     // [384]
    float* sAc   = fb + 448;    // [128]

    int tid = threadIdx.x;
    int pix0 = blockIdx.x * 64;
    int bi = pix0 >> 16;
    int hw0 = pix0 & 65535;

    {
        const uint4* gW = (const uint4*)g_Wh;
        uint4* sW = (uint4*)sWh;
        #pragma unroll
        for (int q = tid; q < 3072; q += 512) sW[q] = gW[q];
    }
    {
        const float* xg = x + (size_t)bi * CIN * PLANE + hw0;
        #pragma unroll
        for (int q = tid; q < 4096; q += 512) {
            int c = q >> 6, p = q & 63;
            float v = xg[(size_t)c * PLANE + p];
            sXt[(p << 6) + (((c >> 3) ^ (p & 7)) << 3) + (c & 7)] = __float2half(v);
        }
    }
    if (tid < 64) ps[tid] = g_prior[pix0 + tid];
    if (tid >= 64 && tid < 448) sball[tid - 64] = g_ball[tid - 64];
    if (tid >= 384) sAc[tid - 384] = g_Aconst[tid - 384];
    __syncthreads();

    int w = tid >> 5, lane = tid & 31;
    int wp = w & 7, jw = w >> 3;
    int lr = lane & 15;
    int lh = lane >> 4;

    float acc[4][3][4];
    #pragma unroll
    for (int i = 0; i < 4; i++)
        #pragma unroll
        for (int j = 0; j < 3; j++)
            #pragma unroll
            for (int q = 0; q < 4; q++) acc[i][j][q] = 0.f;

    #pragma unroll
    for (int kc = 0; kc < 4; kc++) {
        unsigned a[4][4];
        #pragma unroll
        for (int ma = 0; ma < 4; ma++) {
            int row = ma * 16 + lr;
            int colb = kc * 16 + lh * 8;
            unsigned addr = s2u(&sXt[(row << 6) + (((colb >> 3) ^ (row & 7)) << 3)]);
            ldsm_x4(a[ma], addr);
        }
        unsigned b[3][2];
        #pragma unroll
        for (int r3 = 0; r3 < 3; r3++) {
            int na = r3 * 16 + wp * 2 + jw;
            int k = kc * 16 + lr;
            int nb = na * 8;
            unsigned addr = s2u(&sWh[k * 384 + (((nb >> 3) ^ (k & 7)) << 3)]);
            ldsm_x2t(b[r3], addr);
        }
        #pragma unroll
        for (int ma = 0; ma < 4; ma++)
            #pragma unroll
            for (int r3 = 0; r3 < 3; r3++)
                mma16816(acc[ma][r3], a[ma], b[r3]);
    }
    __syncthreads();

    __half* sA = sm;            // [128][72]
    __half* sB = sm + 9216;     // [128][72]
    float lam = *lam_p;
    float alp = *alp_p;

    #pragma unroll
    for (int i = 0; i < 2; i++) {
        int c = wp * 16 + jw * 8 + (lane & 3) * 2 + i;
        float bin = sball[3 * c];
        float bdl = sball[3 * c + 1];
        float bbb = sball[3 * c + 2];
        float Ac  = sAc[c];
        #pragma unroll
        for (int ma = 0; ma < 4; ma++) {
            #pragma unroll
            for (int rr = 0; rr < 2; rr++) {
                int px = ma * 16 + (lane >> 2) + rr * 8;
                int idx = rr * 2 + i;
                float p = ps[px];
                float xp   = acc[ma][0][idx] + bin;
                float dpre = acc[ma][1][idx] + bdl + lam * p;
                float delta = fmaxf(dpre, 0.f) + log1pf(__expf(-fabsf(dpre)));
                float bk = (acc[ma][2][idx] + bbb) * (1.f + alp * p);
                sA[c * 72 + px] = __float2half(__expf(delta * Ac));
                sB[c * 72 + px] = __float2half(delta * bk * xp);
            }
        }
    }
    __syncthreads();

    size_t ob = (size_t)bi * HID * PLANE + hw0;
    #pragma unroll
    for (int q = tid; q < 1024; q += 512) {
        int c = q >> 3, p8 = (q & 7) * 8;
        *(uint4*)&g_Abar[ob + (size_t)c * PLANE + p8] = *(const uint4*)&sA[c * 72 + p8];
        *(uint4*)&g_bx[ob + (size_t)c * PLANE + p8]   = *(const uint4*)&sB[c * 72 + p8];
    }
}

// ============================================================
// K_scanH: block = 256 rows x 64-col strip of one plane. Single DRAM pass.
// ============================================================
#define SMEM_SH (65536 + 4096)

__global__ __launch_bounds__(256) void kscanH()
{
    extern __shared__ __half2 sh2[];
    __half2* sA2 = sh2;              // [256][32] half2
    __half2* sB2 = sh2 + 8192;
    float2* AcS  = (float2*)(sh2 + 16384);   // [8][32]
    float2* BcS  = AcS + 256;

    int tid = threadIdx.x;
    int blk = blockIdx.x;
    size_t gbase = (size_t)(blk >> 2) * PLANE + (size_t)(blk & 3) * 64;
    size_t gb2 = gbase >> 1;

    {
        const __half* gA = g_Abar + gbase;
        const __half* gB = g_bx + gbase;
        #pragma unroll
        for (int q = tid; q < 2048; q += 256) {
            int r = q >> 3, g = q & 7;
            *(uint4*)&sA2[r * 32 + g * 4] = *(const uint4*)&gA[(size_t)r * 256 + g * 8];
            *(uint4*)&sB2[r * 32 + g * 4] = *(const uint4*)&gB[(size_t)r * 256 + g * 8];
        }
    }
    __syncthreads();

    int col2 = tid & 31;
    int chunk = tid >> 5;
    int r0 = chunk * 32;

    float2 Ac = make_float2(1.f, 1.f), Bc = make_float2(0.f, 0.f);
    #pragma unroll 8
    for (int r = 0; r < 32; r++) {
        float2 a = __half22float2(sA2[(r0 + r) * 32 + col2]);
        float2 b = __half22float2(sB2[(r0 + r) * 32 + col2]);
        Bc.x = fmaf(a.x, Bc.x, b.x); Bc.y = fmaf(a.y, Bc.y, b.y);
        Ac.x *= a.x; Ac.y *= a.y;
    }
    AcS[tid] = Ac; BcS[tid] = Bc;
    __syncthreads();

    float2 h = make_float2(0.f, 0.f);
    for (int k = 0; k < chunk; k++) {
        float2 A = AcS[k * 32 + col2];
        float2 B = BcS[k * 32 + col2];
        h.x = fmaf(A.x, h.x, B.x); h.y = fmaf(A.y, h.y, B.y);
    }

    __half2* S2 = (__half2*)g_sH;
    #pragma unroll 8
    for (int r = 0; r < 32; r++) {
        float2 a = __half22float2(sA2[(r0 + r) * 32 + col2]);
        float2 b = __half22float2(sB2[(r0 + r) * 32 + col2]);
        h.x = fmaf(a.x, h.x, b.x); h.y = fmaf(a.y, h.y, b.y);
        S2[gb2 + (size_t)(r0 + r) * 128 + col2] = __floats2half2_rn(h.x, h.y);
    }
}

// ============================================================
// K_scanWout: FUSED W-scan + sum(sH) + output GEMM + residual store.
// Block = one (batch, H-row): 128 channels x 256 px. 512 threads / 16 warps.
// Phase 1: warp w scans channels w*8..w*8+7 from global, s -> swizzled smem.
// Phase 2: mma GEMM D[256px,64co] = S[256,128] @ Wo[128,64];
//          out = x + gamma*(D + b_out).
// ============================================================
#define SMEM_SWO (82176)

__device__ __forceinline__ void unpack8h(uint4 u, float* f) {
    float2 t;
    t = __half22float2(*(__half2*)&u.x); f[0] = t.x; f[1] = t.y;
    t = __half22float2(*(__half2*)&u.y); f[2] = t.x; f[3] = t.y;
    t = __half22float2(*(__half2*)&u.z); f[4] = t.x; f[5] = t.y;
    t = __half22float2(*(__half2*)&u.w); f[6] = t.x; f[7] = t.y;
}

__global__ __launch_bounds__(512) void kscanWout(
    const float* __restrict__ x,
    const float* __restrict__ b_out,
    const float* __restrict__ gam_p,
    float* __restrict__ out)
{
    extern __shared__ __half sm[];
    __half* sS  = sm;                       // [k=128][px=256] swizzled (64KB)
    __half* sWo = sm + 32768;               // [k=128][co=64] swizzled (16KB)
    float* sbo  = (float*)(sm + 40960);     // [64]

    int tid = threadIdx.x;
    int w = tid >> 5, lane = tid & 31;
    int bi = blockIdx.x >> 8;
    int y  = blockIdx.x & 255;

    // Wo + bias staging
    {
        const uint4* gW = (const uint4*)g_Woh;
        uint4* sW = (uint4*)sWo;
        #pragma unroll
        for (int q = tid; q < 1024; q += 512) sW[q] = gW[q];
    }
    if (tid < 64) sbo[tid] = b_out[tid];

    // ---- Phase 1: W-scan 8 channels per warp, fused + sH, write swizzled s ----
    #pragma unroll 1
    for (int i = 0; i < 8; i++) {
        int c = w * 8 + i;
        size_t base = ((size_t)(bi * HID + c)) * PLANE + (size_t)y * 256 + lane * 8;

        uint4 ua = *(const uint4*)(g_Abar + base);
        uint4 ub = *(const uint4*)(g_bx + base);
        uint4 us = *(const uint4*)(g_sH + base);
        float a[8], b[8], s[8];
        unpack8h(ua, a); unpack8h(ub, b); unpack8h(us, s);

        float Ac = 1.f, Bc = 0.f;
        #pragma unroll
        for (int j = 0; j < 8; j++) {
            Bc = fmaf(a[j], Bc, b[j]);
            Ac = a[j] * Ac;
        }
        #pragma unroll
        for (int d = 1; d < 32; d <<= 1) {
            float Ap = __shfl_up_sync(0xffffffffu, Ac, d);
            float Bp = __shfl_up_sync(0xffffffffu, Bc, d);
            if (lane >= d) {
                Bc = fmaf(Ac, Bp, Bc);
                Ac = Ac * Ap;
            }
        }
        float hin = __shfl_up_sync(0xffffffffu, Bc, 1);
        if (lane == 0) hin = 0.f;

        float h = hin, r[8];
        #pragma unroll
        for (int j = 0; j < 8; j++) {
            h = fmaf(a[j], h, b[j]);
            r[j] = h + s[j];
        }
        union { uint4 u; __half2 hh[4]; } o;
        o.hh[0] = __floats2half2_rn(r[0], r[1]);
        o.hh[1] = __floats2half2_rn(r[2], r[3]);
        o.hh[2] = __floats2half2_rn(r[4], r[5]);
        o.hh[3] = __floats2half2_rn(r[6], r[7]);
        *(uint4*)&sS[c * 256 + ((lane ^ (c & 7)) << 3)] = o.u;
    }
    __syncthreads();

    // ---- Phase 2: GEMM. Warp w owns m-atom w (16 px), all 8 co-atoms. ----
    float acc[8][4];
    #pragma unroll
    for (int j = 0; j < 8; j++)
        #pragma unroll
        for (int q = 0; q < 4; q++) acc[j][q] = 0.f;

    int kr = lane & 7, sel = lane >> 3;
    #pragma unroll
    for (int kc = 0; kc < 8; kc++) {
        unsigned a[4];
        {
            int krow = kc * 16 + ((sel >> 1) << 3) + kr;
            int mcol = w * 16 + ((sel & 1) << 3);
            unsigned addr = s2u(&sS[krow * 256 + (((mcol >> 3) ^ (krow & 7)) << 3)]);
            ldsm_x4t(a, addr);
        }
        #pragma unroll
        for (int jp = 0; jp < 4; jp++) {
            unsigned b4[4];
            int k = kc * 16 + (lane & 15);
            int cog = jp * 2 + (lane >> 4);
            unsigned addr = s2u(&sWo[k * 64 + ((cog ^ (k & 7)) << 3)]);
            ldsm_x4t(b4, addr);
            mma16816(acc[jp * 2], a, b4);
            mma16816(acc[jp * 2 + 1], a, b4 + 2);
        }
    }
    __syncthreads();   // all sS reads done -> reuse as sD

    // stage D [co][256 px] fp32 (64KB, overwrites sS)
    float* sD = (float*)sm;
    {
        int px = w * 16 + (lane >> 2);
        #pragma unroll
        for (int na = 0; na < 8; na++) {
            int co = na * 8 + (lane & 3) * 2;
            sD[co * 256 + px]            = acc[na][0];
            sD[(co + 1) * 256 + px]      = acc[na][1];
            sD[co * 256 + px + 8]        = acc[na][2];
            sD[(co + 1) * 256 + px + 8]  = acc[na][3];
        }
    }
    __syncthreads();

    float gam = *gam_p;
    #pragma unroll
    for (int q = tid; q < 4096; q += 512) {
        int co = q >> 6, p4 = (q & 63) * 4;
        float bo = sbo[co];
        size_t base = (size_t)bi * CIN * PLANE + (size_t)co * PLANE + (size_t)y * 256 + p4;
        float4 xg = *(const float4*)&x[base];
        float4 dv = *(const float4*)&sD[co * 256 + p4];
        float4 o;
        o.x = fmaf(gam, dv.x + bo, xg.x);
        o.y = fmaf(gam, dv.y + bo, xg.y);
        o.z = fmaf(gam, dv.z + bo, xg.z);
        o.w = fmaf(gam, dv.w + bo, xg.w);
        *(float4*)&out[base] = o;
    }
}

// ============================================================
extern "C" void kernel_launch(void* const* d_in, const int* in_sizes, int n_in,
                              void* d_out, int out_size)
{
    const float* x       = (const float*)d_in[0];
    const float* prior   = (const float*)d_in[1];
    const float* W_in    = (const float*)d_in[2];
    const float* b_in    = (const float*)d_in[3];
    const float* W_out   = (const float*)d_in[4];
    const float* b_out   = (const float*)d_in[5];
    const float* W_delta = (const float*)d_in[6];
    const float* b_delta = (const float*)d_in[7];
    const float* W_B     = (const float*)d_in[8];
    const float* b_B     = (const float*)d_in[9];
    const float* A_param = (const float*)d_in[10];
    const float* lam     = (const float*)d_in[11];
    const float* alp     = (const float*)d_in[12];
    const float* gam     = (const float*)d_in[13];
    float* out = (float*)d_out;

    cudaFuncSetAttribute(kproj, cudaFuncAttributeMaxDynamicSharedMemorySize, SMEM_KP);
    cudaFuncSetAttribute(kscanH, cudaFuncAttributeMaxDynamicSharedMemorySize, SMEM_SH);
    cudaFuncSetAttribute(kscanWout, cudaFuncAttributeMaxDynamicSharedMemorySize, SMEM_SWO);

    kpre<<<130, 256>>>(W_in, b_in, W_delta, b_delta, W_B, b_B, A_param, W_out);
    kprior<<<NPIX / 256, 256>>>(prior, out + OUT2);
    kproj<<<NPIX / 64, 512, SMEM_KP>>>(x, lam, alp);
    kscanH<<<2048, 256, SMEM_SH>>>();
    kscanWout<<<BATCH * 256, 512, SMEM_SWO>>>(x, b_out, gam, out);
}

// round 8
// speedup vs baseline: 3.5830x; 1.1480x over previous
#include <cuda_runtime.h>
#include <cuda_fp16.h>

#define BATCH 4
#define CIN   64
#define HID   128
#define PLANE 65536          // 256*256
#define NPIX  262144         // BATCH*PLANE
#define NELEM 33554432       // BATCH*HID*PLANE
#define OUT2  16777216       // BATCH*CIN*PLANE  (offset of prior_up in d_out)

// -------- scratch (static device globals: no allocation allowed) --------
__device__ float  g_ball[384];        // combined biases, index 3c+role
__device__ float  g_Aconst[HID];      // -exp(A_param)
__device__ float  g_prior[NPIX];      // clipped upsampled prior
__device__ __align__(16) __half g_Wh[64 * 384];   // fp16 proj weights [k][n], n=role*128+c, swizzled
__device__ __align__(16) __half g_Woh[128 * 64];  // fp16 W_out [k][co], swizzled
__device__ __half g_Abar[NELEM];
__device__ __half g_bx[NELEM];
__device__ __half g_sH[NELEM];        // H-scan result

__device__ __forceinline__ unsigned s2u(const void* p) {
    return (unsigned)__cvta_generic_to_shared(p);
}
__device__ __forceinline__ void ldsm_x4(unsigned* r, unsigned addr) {
    asm volatile("ldmatrix.sync.aligned.m8n8.x4.shared.b16 {%0,%1,%2,%3}, [%4];"
                 : "=r"(r[0]), "=r"(r[1]), "=r"(r[2]), "=r"(r[3]) : "r"(addr));
}
__device__ __forceinline__ void ldsm_x4t(unsigned* r, unsigned addr) {
    asm volatile("ldmatrix.sync.aligned.m8n8.x4.trans.shared.b16 {%0,%1,%2,%3}, [%4];"
                 : "=r"(r[0]), "=r"(r[1]), "=r"(r[2]), "=r"(r[3]) : "r"(addr));
}
__device__ __forceinline__ void ldsm_x2t(unsigned* r, unsigned addr) {
    asm volatile("ldmatrix.sync.aligned.m8n8.x2.trans.shared.b16 {%0,%1}, [%2];"
                 : "=r"(r[0]), "=r"(r[1]) : "r"(addr));
}
__device__ __forceinline__ void mma16816(float* d, const unsigned* a, const unsigned* b) {
    asm volatile("mma.sync.aligned.m16n8k16.row.col.f32.f16.f16.f32 "
                 "{%0,%1,%2,%3},{%4,%5,%6,%7},{%8,%9},{%0,%1,%2,%3};"
                 : "+f"(d[0]), "+f"(d[1]), "+f"(d[2]), "+f"(d[3])
                 : "r"(a[0]), "r"(a[1]), "r"(a[2]), "r"(a[3]), "r"(b[0]), "r"(b[1]));
}
__device__ __forceinline__ void cpa16(unsigned saddr, const void* g) {
    asm volatile("cp.async.cg.shared.global [%0], [%1], 16;" :: "r"(saddr), "l"(g));
}
__device__ __forceinline__ void cpa_commit() {
    asm volatile("cp.async.commit_group;");
}

// ============================================================
// K_pre: combined fp16 weights + biases + A_const + fp16 W_out
// ============================================================
__global__ __launch_bounds__(256) void kpre(
    const float* __restrict__ W_in, const float* __restrict__ b_in,
    const float* __restrict__ W_delta, const float* __restrict__ b_delta,
    const float* __restrict__ W_B, const float* __restrict__ b_B,
    const float* __restrict__ A_param, const float* __restrict__ W_out)
{
    int idx = blockIdx.x * 256 + threadIdx.x;
    if (idx < 384 * 64) {
        int r = idx >> 6, k = idx & 63;
        int c = r / 3, q = r - 3 * c;
        float v;
        if (q == 0) {
            v = W_in[c * 64 + k];
        } else {
            const float* Wm = (q == 1) ? W_delta : W_B;
            float s = 0.f;
            #pragma unroll 4
            for (int j = 0; j < 128; j++) s = fmaf(Wm[c * 128 + j], W_in[j * 64 + k], s);
            v = s;
        }
        int n = q * 128 + c;
        g_Wh[k * 384 + (((n >> 3) ^ (k & 7)) << 3) + (n & 7)] = __float2half(v);
    } else if (idx < 384 * 64 + 384) {
        int r = idx - 384 * 64;
        int c = r / 3, q = r - 3 * c;
        float v;
        if (q == 0) {
            v = b_in[c];
        } else {
            const float* Wm = (q == 1) ? W_delta : W_B;
            const float* bm = (q == 1) ? b_delta : b_B;
            float s = bm[c];
            #pragma unroll 4
            for (int j = 0; j < 128; j++) s = fmaf(Wm[c * 128 + j], b_in[j], s);
            v = s;
        }
        g_ball[r] = v;
    } else if (idx < 384 * 64 + 384 + HID) {
        int c = idx - (384 * 64 + 384);
        g_Aconst[c] = -expf(A_param[c]);
    } else if (idx < 384 * 64 + 384 + HID + 128 * 64) {
        int t = idx - (384 * 64 + 384 + HID);
        int k = t >> 6, co = t & 63;
        g_Woh[k * 64 + (((co >> 3) ^ (k & 7)) << 3) + (co & 7)] =
            __float2half(W_out[co * 128 + k]);
    }
}

// ============================================================
// K_prior: bilinear (align_corners) 64x64 -> 256x256, clip [-1,1]
// ============================================================
__global__ __launch_bounds__(256) void kprior(
    const float* __restrict__ prior, float* __restrict__ out2)
{
    int tid = blockIdx.x * 256 + threadIdx.x;
    int bi = tid >> 16;
    int hw = tid & 65535;
    int oy = hw >> 8, ox = hw & 255;

    float fy = (float)(oy * 63) / 255.0f;
    float fx = (float)(ox * 63) / 255.0f;
    int y0 = (int)fy; int y1 = min(y0 + 1, 63);
    int x0 = (int)fx; int x1 = min(x0 + 1, 63);
    float wy = fy - (float)y0;
    float wx = fx - (float)x0;

    const float* p = prior + bi * 4096;
    float v00 = p[y0 * 64 + x0], v10 = p[y1 * 64 + x0];
    float v01 = p[y0 * 64 + x1], v11 = p[y1 * 64 + x1];
    float r0 = v00 * (1.f - wy) + v10 * wy;
    float r1 = v01 * (1.f - wy) + v11 * wy;
    float val = r0 * (1.f - wx) + r1 * wx;
    val = fminf(fmaxf(val, -1.f), 1.f);

    g_prior[tid] = val;
    out2[tid] = val;
}

// ============================================================
// K_proj: cp.async pipelined. Block = 4 consecutive 64-px tiles.
// Per tile: mma D[64,384] = Xt @ Wh, epilogue -> Abar/bx.
// smem layout (bytes):
//   sWh   @ 0      : 49152 (24576 half)
//   xraw  @ 49152  : 32768 (2 bufs x 4096 float)
//   sXt   @ 81920  : 8192  (4096 half)
//   sA    @ 90112  : 18432 (128*72 half)
//   sB    @ 108544 : 18432
//   consts@ 126976 : 3072  (sps 256, sball 384, sAc 128 floats)
// ============================================================
#define SMEM_KP 130048

__global__ __launch_bounds__(512) void kproj(
    const float* __restrict__ x,
    const float* __restrict__ lam_p,
    const float* __restrict__ alp_p)
{
    extern __shared__ char smc[];
    __half* sWh  = (__half*)smc;
    float*  xraw = (float*)(smc + 49152);           // [2][4096]
    __half* sXt  = (__half*)(smc + 81920);
    __half* sA   = (__half*)(smc + 90112);          // [128][72]
    __half* sB   = (__half*)(smc + 108544);
    float*  sps  = (float*)(smc + 126976);          // [256]
    float*  sball = sps + 256;                      // [384]
    float*  sAc   = sball + 384;                    // [128]

    int tid = threadIdx.x;
    int pixB = blockIdx.x * 256;
    int bi = pixB >> 16;
    int hwB = pixB & 65535;
    const float* xg = x + (size_t)bi * CIN * PLANE + hwB;

    // G0: weights
    {
        unsigned sw = s2u(sWh);
        #pragma unroll
        for (int q = tid; q < 3072; q += 512)
            cpa16(sw + q * 16, (const char*)g_Wh + q * 16);
        cpa_commit();
    }
    // G1, G2: x tiles 0,1
    #pragma unroll
    for (int t0 = 0; t0 < 2; t0++) {
        unsigned sx = s2u(xraw + t0 * 4096);
        const float* gt = xg + t0 * 64;
        #pragma unroll
        for (int q = tid; q < 1024; q += 512) {
            int c = q >> 4, seg = q & 15;
            cpa16(sx + (c * 64 + seg * 4) * 4, gt + (size_t)c * PLANE + seg * 4);
        }
        cpa_commit();
    }
    // constants (normal loads)
    if (tid < 256) sps[tid] = g_prior[pixB + tid];
    if (tid < 384) sball[tid] = g_ball[tid];
    if (tid < 128) sAc[tid] = g_Aconst[tid];

    int w = tid >> 5, lane = tid & 31;
    int wp = w & 7, jw = w >> 3;
    int lr = lane & 15;
    int lh = lane >> 4;
    float lam = *lam_p;
    float alp = *alp_p;

    #pragma unroll 1
    for (int t = 0; t < 4; t++) {
        if (t < 3) asm volatile("cp.async.wait_group 1;");
        else       asm volatile("cp.async.wait_group 0;");
        __syncthreads();

        // convert tile t (buf t&1) -> swizzled fp16 Xt[p][c]
        const float* xr = xraw + (t & 1) * 4096;
        #pragma unroll
        for (int q = tid; q < 4096; q += 512) {
            int c = q >> 6, p = q & 63;
            sXt[(p << 6) + (((c >> 3) ^ (p & 7)) << 3) + (c & 7)] = __float2half(xr[c * 64 + p]);
        }
        __syncthreads();

        // prefetch tile t+2 into the buffer just freed
        if (t + 2 < 4) {
            unsigned sx = s2u(xraw + (t & 1) * 4096);
            const float* gt = xg + (t + 2) * 64;
            #pragma unroll
            for (int q = tid; q < 1024; q += 512) {
                int c = q >> 4, seg = q & 15;
                cpa16(sx + (c * 64 + seg * 4) * 4, gt + (size_t)c * PLANE + seg * 4);
            }
            cpa_commit();
        }

        // mma
        float acc[4][3][4];
        #pragma unroll
        for (int i = 0; i < 4; i++)
            #pragma unroll
            for (int j = 0; j < 3; j++)
                #pragma unroll
                for (int q = 0; q < 4; q++) acc[i][j][q] = 0.f;

        #pragma unroll
        for (int kc = 0; kc < 4; kc++) {
            unsigned a[4][4];
            #pragma unroll
            for (int ma = 0; ma < 4; ma++) {
                int row = ma * 16 + lr;
                int colb = kc * 16 + lh * 8;
                unsigned addr = s2u(&sXt[(row << 6) + (((colb >> 3) ^ (row & 7)) << 3)]);
                ldsm_x4(a[ma], addr);
            }
            unsigned b[3][2];
            #pragma unroll
            for (int r3 = 0; r3 < 3; r3++) {
                int na = r3 * 16 + wp * 2 + jw;
                int k = kc * 16 + lr;
                int nb = na * 8;
                unsigned addr = s2u(&sWh[k * 384 + (((nb >> 3) ^ (k & 7)) << 3)]);
                ldsm_x2t(b[r3], addr);
            }
            #pragma unroll
            for (int ma = 0; ma < 4; ma++)
                #pragma unroll
                for (int r3 = 0; r3 < 3; r3++)
                    mma16816(acc[ma][r3], a[ma], b[r3]);
        }

        // epilogue -> sA/sB
        #pragma unroll
        for (int i = 0; i < 2; i++) {
            int c = wp * 16 + jw * 8 + (lane & 3) * 2 + i;
            float bin = sball[3 * c];
            float bdl = sball[3 * c + 1];
            float bbb = sball[3 * c + 2];
            float Ac  = sAc[c];
            #pragma unroll
            for (int ma = 0; ma < 4; ma++) {
                #pragma unroll
                for (int rr = 0; rr < 2; rr++) {
                    int px = ma * 16 + (lane >> 2) + rr * 8;
                    int idx = rr * 2 + i;
                    float p = sps[t * 64 + px];
                    float xp   = acc[ma][0][idx] + bin;
                    float dpre = acc[ma][1][idx] + bdl + lam * p;
                    float delta = fmaxf(dpre, 0.f) + __logf(1.f + __expf(-fabsf(dpre)));
                    float bk = (acc[ma][2][idx] + bbb) * (1.f + alp * p);
                    sA[c * 72 + px] = __float2half(__expf(delta * Ac));
                    sB[c * 72 + px] = __float2half(delta * bk * xp);
                }
            }
        }
        __syncthreads();

        // coalesced stores
        size_t ob = (size_t)bi * HID * PLANE + hwB + t * 64;
        #pragma unroll
        for (int q = tid; q < 1024; q += 512) {
            int c = q >> 3, p8 = (q & 7) * 8;
            *(uint4*)&g_Abar[ob + (size_t)c * PLANE + p8] = *(const uint4*)&sA[c * 72 + p8];
            *(uint4*)&g_bx[ob + (size_t)c * PLANE + p8]   = *(const uint4*)&sB[c * 72 + p8];
        }
    }
}

// ============================================================
// K_scanH: block = 256 rows x 64-col strip of one plane. Single DRAM pass.
// ============================================================
#define SMEM_SH (65536 + 4096)

__global__ __launch_bounds__(256) void kscanH()
{
    extern __shared__ __half2 sh2[];
    __half2* sA2 = sh2;              // [256][32] half2
    __half2* sB2 = sh2 + 8192;
    float2* AcS  = (float2*)(sh2 + 16384);   // [8][32]
    float2* BcS  = AcS + 256;

    int tid = threadIdx.x;
    int blk = blockIdx.x;
    size_t gbase = (size_t)(blk >> 2) * PLANE + (size_t)(blk & 3) * 64;
    size_t gb2 = gbase >> 1;

    {
        const __half* gA = g_Abar + gbase;
        const __half* gB = g_bx + gbase;
        #pragma unroll
        for (int q = tid; q < 2048; q += 256) {
            int r = q >> 3, g = q & 7;
            *(uint4*)&sA2[r * 32 + g * 4] = *(const uint4*)&gA[(size_t)r * 256 + g * 8];
            *(uint4*)&sB2[r * 32 + g * 4] = *(const uint4*)&gB[(size_t)r * 256 + g * 8];
        }
    }
    __syncthreads();

    int col2 = tid & 31;
    int chunk = tid >> 5;
    int r0 = chunk * 32;

    float2 Ac = make_float2(1.f, 1.f), Bc = make_float2(0.f, 0.f);
    #pragma unroll 8
    for (int r = 0; r < 32; r++) {
        float2 a = __half22float2(sA2[(r0 + r) * 32 + col2]);
        float2 b = __half22float2(sB2[(r0 + r) * 32 + col2]);
        Bc.x = fmaf(a.x, Bc.x, b.x); Bc.y = fmaf(a.y, Bc.y, b.y);
        Ac.x *= a.x; Ac.y *= a.y;
    }
    AcS[tid] = Ac; BcS[tid] = Bc;
    __syncthreads();

    float2 h = make_float2(0.f, 0.f);
    for (int k = 0; k < chunk; k++) {
        float2 A = AcS[k * 32 + col2];
        float2 B = BcS[k * 32 + col2];
        h.x = fmaf(A.x, h.x, B.x); h.y = fmaf(A.y, h.y, B.y);
    }

    __half2* S2 = (__half2*)g_sH;
    #pragma unroll 8
    for (int r = 0; r < 32; r++) {
        float2 a = __half22float2(sA2[(r0 + r) * 32 + col2]);
        float2 b = __half22float2(sB2[(r0 + r) * 32 + col2]);
        h.x = fmaf(a.x, h.x, b.x); h.y = fmaf(a.y, h.y, b.y);
        S2[gb2 + (size_t)(r0 + r) * 128 + col2] = __floats2half2_rn(h.x, h.y);
    }
}

// ============================================================
// K_scanWout: FUSED W-scan + sum(sH) + output GEMM + direct residual store.
// Block = one (batch, H-row): 128 channels x 256 px. 512 threads / 16 warps.
// ============================================================
#define SMEM_SWO (82176)

__device__ __forceinline__ void unpack8h(uint4 u, float* f) {
    float2 t;
    t = __half22float2(*(__half2*)&u.x); f[0] = t.x; f[1] = t.y;
    t = __half22float2(*(__half2*)&u.y); f[2] = t.x; f[3] = t.y;
    t = __half22float2(*(__half2*)&u.z); f[4] = t.x; f[5] = t.y;
    t = __half22float2(*(__half2*)&u.w); f[6] = t.x; f[7] = t.y;
}

__global__ __launch_bounds__(512, 2) void kscanWout(
    const float* __restrict__ x,
    const float* __restrict__ b_out,
    const float* __restrict__ gam_p,
    float* __restrict__ out)
{
    extern __shared__ __half sm[];
    __half* sS  = sm;                       // [k=128][px=256] swizzled (64KB)
    __half* sWo = sm + 32768;               // [k=128][co=64] swizzled (16KB)
    float* sbo  = (float*)(sm + 40960);     // [64]

    int tid = threadIdx.x;
    int w = tid >> 5, lane = tid & 31;
    int bi = blockIdx.x >> 8;
    int y  = blockIdx.x & 255;

    {
        const uint4* gW = (const uint4*)g_Woh;
        uint4* sW = (uint4*)sWo;
        #pragma unroll
        for (int q = tid; q < 1024; q += 512) sW[q] = gW[q];
    }
    if (tid < 64) sbo[tid] = b_out[tid];

    // ---- Phase 1: W-scan 8 channels per warp, fused + sH, write swizzled s ----
    #pragma unroll 1
    for (int i = 0; i < 8; i++) {
        int c = w * 8 + i;
        size_t base = ((size_t)(bi * HID + c)) * PLANE + (size_t)y * 256 + lane * 8;

        uint4 ua = *(const uint4*)(g_Abar + base);
        uint4 ub = *(const uint4*)(g_bx + base);
        uint4 us = *(const uint4*)(g_sH + base);
        float a[8], b[8], s[8];
        unpack8h(ua, a); unpack8h(ub, b); unpack8h(us, s);

        float Ac = 1.f, Bc = 0.f;
        #pragma unroll
        for (int j = 0; j < 8; j++) {
            Bc = fmaf(a[j], Bc, b[j]);
            Ac = a[j] * Ac;
        }
        #pragma unroll
        for (int d = 1; d < 32; d <<= 1) {
            float Ap = __shfl_up_sync(0xffffffffu, Ac, d);
            float Bp = __shfl_up_sync(0xffffffffu, Bc, d);
            if (lane >= d) {
                Bc = fmaf(Ac, Bp, Bc);
                Ac = Ac * Ap;
            }
        }
        float hin = __shfl_up_sync(0xffffffffu, Bc, 1);
        if (lane == 0) hin = 0.f;

        float h = hin, r[8];
        #pragma unroll
        for (int j = 0; j < 8; j++) {
            h = fmaf(a[j], h, b[j]);
            r[j] = h + s[j];
        }
        union { uint4 u; __half2 hh[4]; } o;
        o.hh[0] = __floats2half2_rn(r[0], r[1]);
        o.hh[1] = __floats2half2_rn(r[2], r[3]);
        o.hh[2] = __floats2half2_rn(r[4], r[5]);
        o.hh[3] = __floats2half2_rn(r[6], r[7]);
        *(uint4*)&sS[c * 256 + ((lane ^ (c & 7)) << 3)] = o.u;
    }
    __syncthreads();

    // ---- Phase 2: GEMM. Warp w owns m-atom w (16 px), all 8 co-atoms. ----
    float acc[8][4];
    #pragma unroll
    for (int j = 0; j < 8; j++)
        #pragma unroll
        for (int q = 0; q < 4; q++) acc[j][q] = 0.f;

    int kr = lane & 7, sel = lane >> 3;
    #pragma unroll
    for (int kc = 0; kc < 8; kc++) {
        unsigned a[4];
        {
            int krow = kc * 16 + ((sel >> 1) << 3) + kr;
            int mcol = w * 16 + ((sel & 1) << 3);
            unsigned addr = s2u(&sS[krow * 256 + (((mcol >> 3) ^ (krow & 7)) << 3)]);
            ldsm_x4t(a, addr);
        }
        #pragma unroll
        for (int jp = 0; jp < 4; jp++) {
            unsigned b4[4];
            int k = kc * 16 + (lane & 15);
            int cog = jp * 2 + (lane >> 4);
            unsigned addr = s2u(&sWo[k * 64 + ((cog ^ (k & 7)) << 3)]);
            ldsm_x4t(b4, addr);
            mma16816(acc[jp * 2], a, b4);
            mma16816(acc[jp * 2 + 1], a, b4 + 2);
        }
    }

    // ---- direct epilogue: 32B-sector loads/stores, no smem staging ----
    float gam = *gam_p;
    int px = w * 16 + (lane >> 2);
    size_t rowb = (size_t)bi * CIN * PLANE + (size_t)y * 256;
    #pragma unroll
    for (int na = 0; na < 8; na++) {
        int co = na * 8 + (lane & 3) * 2;
        float bo0 = sbo[co], bo1 = sbo[co + 1];
        size_t b0 = rowb + (size_t)co * PLANE + px;
        out[b0]             = fmaf(gam, acc[na][0] + bo0, x[b0]);
        out[b0 + PLANE]     = fmaf(gam, acc[na][1] + bo1, x[b0 + PLANE]);
        out[b0 + 8]         = fmaf(gam, acc[na][2] + bo0, x[b0 + 8]);
        out[b0 + PLANE + 8] = fmaf(gam, acc[na][3] + bo1, x[b0 + PLANE + 8]);
    }
}

// ============================================================
extern "C" void kernel_launch(void* const* d_in, const int* in_sizes, int n_in,
                              void* d_out, int out_size)
{
    const float* x       = (const float*)d_in[0];
    const float* prior   = (const float*)d_in[1];
    const float* W_in    = (const float*)d_in[2];
    const float* b_in    = (const float*)d_in[3];
    const float* W_out   = (const float*)d_in[4];
    const float* b_out   = (const float*)d_in[5];
    const float* W_delta = (const float*)d_in[6];
    const float* b_delta = (const float*)d_in[7];
    const float* W_B     = (const float*)d_in[8];
    const float* b_B     = (const float*)d_in[9];
    const float* A_param = (const float*)d_in[10];
    const float* lam     = (const float*)d_in[11];
    const float* alp     = (const float*)d_in[12];
    const float* gam     = (const float*)d_in[13];
    float* out = (float*)d_out;

    cudaFuncSetAttribute(kproj, cudaFuncAttributeMaxDynamicSharedMemorySize, SMEM_KP);
    cudaFuncSetAttribute(kscanH, cudaFuncAttributeMaxDynamicSharedMemorySize, SMEM_SH);
    cudaFuncSetAttribute(kscanWout, cudaFuncAttributeMaxDynamicSharedMemorySize, SMEM_SWO);

    kpre<<<130, 256>>>(W_in, b_in, W_delta, b_delta, W_B, b_B, A_param, W_out);
    kprior<<<NPIX / 256, 256>>>(prior, out + OUT2);
    kproj<<<NPIX / 256, 512, SMEM_KP>>>(x, lam, alp);
    kscanH<<<2048, 256, SMEM_SH>>>();
    kscanWout<<<BATCH * 256, 512, SMEM_SWO>>>(x, b_out, gam, out);
}

// round 9
// speedup vs baseline: 3.7461x; 1.0455x over previous
#include <cuda_runtime.h>
#include <cuda_fp16.h>

#define BATCH 4
#define CIN   64
#define HID   128
#define PLANE 65536          // 256*256
#define NPIX  262144         // BATCH*PLANE
#define NELEM 33554432       // BATCH*HID*PLANE
#define OUT2  16777216       // BATCH*CIN*PLANE  (offset of prior_up in d_out)

// -------- scratch (static device globals: no allocation allowed) --------
__device__ float  g_ball[384];        // combined biases, index 3c+role
__device__ float  g_Aconst[HID];      // -exp(A_param)
__device__ float  g_prior[NPIX];      // clipped upsampled prior
__device__ __align__(16) __half g_Wh[64 * 384];   // fp16 proj weights [k][n], n=role*128+c, swizzled
__device__ __align__(16) __half g_Woh[128 * 64];  // fp16 W_out [k][co], swizzled
__device__ __half g_Abar[NELEM];
__device__ __half g_bx[NELEM];
__device__ __half g_sH[NELEM];        // H-scan result

__device__ __forceinline__ unsigned s2u(const void* p) {
    return (unsigned)__cvta_generic_to_shared(p);
}
__device__ __forceinline__ void ldsm_x4t(unsigned* r, unsigned addr) {
    asm volatile("ldmatrix.sync.aligned.m8n8.x4.trans.shared.b16 {%0,%1,%2,%3}, [%4];"
                 : "=r"(r[0]), "=r"(r[1]), "=r"(r[2]), "=r"(r[3]) : "r"(addr));
}
__device__ __forceinline__ void ldsm_x2t(unsigned* r, unsigned addr) {
    asm volatile("ldmatrix.sync.aligned.m8n8.x2.trans.shared.b16 {%0,%1}, [%2];"
                 : "=r"(r[0]), "=r"(r[1]) : "r"(addr));
}
__device__ __forceinline__ void mma16816(float* d, const unsigned* a, const unsigned* b) {
    asm volatile("mma.sync.aligned.m16n8k16.row.col.f32.f16.f16.f32 "
                 "{%0,%1,%2,%3},{%4,%5,%6,%7},{%8,%9},{%0,%1,%2,%3};"
                 : "+f"(d[0]), "+f"(d[1]), "+f"(d[2]), "+f"(d[3])
                 : "r"(a[0]), "r"(a[1]), "r"(a[2]), "r"(a[3]), "r"(b[0]), "r"(b[1]));
}

// ============================================================
// K_setup: blocks 0..129 = kpre (weights/biases/A_const/W_out fp16),
//          blocks 130..  = kprior (bilinear upsample + clip)
// ============================================================
__global__ __launch_bounds__(256) void ksetup(
    const float* __restrict__ W_in, const float* __restrict__ b_in,
    const float* __restrict__ W_delta, const float* __restrict__ b_delta,
    const float* __restrict__ W_B, const float* __restrict__ b_B,
    const float* __restrict__ A_param, const float* __restrict__ W_out,
    const float* __restrict__ prior, float* __restrict__ out2)
{
    if (blockIdx.x < 130) {
        int idx = blockIdx.x * 256 + threadIdx.x;
        if (idx < 384 * 64) {
            int r = idx >> 6, k = idx & 63;
            int c = r / 3, q = r - 3 * c;
            float v;
            if (q == 0) {
                v = W_in[c * 64 + k];
            } else {
                const float* Wm = (q == 1) ? W_delta : W_B;
                float s = 0.f;
                #pragma unroll 4
                for (int j = 0; j < 128; j++) s = fmaf(Wm[c * 128 + j], W_in[j * 64 + k], s);
                v = s;
            }
            int n = q * 128 + c;
            g_Wh[k * 384 + (((n >> 3) ^ (k & 7)) << 3) + (n & 7)] = __float2half(v);
        } else if (idx < 384 * 64 + 384) {
            int r = idx - 384 * 64;
            int c = r / 3, q = r - 3 * c;
            float v;
            if (q == 0) {
                v = b_in[c];
            } else {
                const float* Wm = (q == 1) ? W_delta : W_B;
                const float* bm = (q == 1) ? b_delta : b_B;
                float s = bm[c];
                #pragma unroll 4
                for (int j = 0; j < 128; j++) s = fmaf(Wm[c * 128 + j], b_in[j], s);
                v = s;
            }
            g_ball[r] = v;
        } else if (idx < 384 * 64 + 384 + HID) {
            int c = idx - (384 * 64 + 384);
            g_Aconst[c] = -expf(A_param[c]);
        } else if (idx < 384 * 64 + 384 + HID + 128 * 64) {
            int t = idx - (384 * 64 + 384 + HID);
            int k = t >> 6, co = t & 63;
            g_Woh[k * 64 + (((co >> 3) ^ (k & 7)) << 3) + (co & 7)] =
                __float2half(W_out[co * 128 + k]);
        }
        return;
    }
    // prior upsample
    int tid = (blockIdx.x - 130) * 256 + threadIdx.x;
    int bi = tid >> 16;
    int hw = tid & 65535;
    int oy = hw >> 8, ox = hw & 255;

    float fy = (float)(oy * 63) / 255.0f;
    float fx = (float)(ox * 63) / 255.0f;
    int y0 = (int)fy; int y1 = min(y0 + 1, 63);
    int x0 = (int)fx; int x1 = min(x0 + 1, 63);
    float wy = fy - (float)y0;
    float wx = fx - (float)x0;

    const float* p = prior + bi * 4096;
    float v00 = p[y0 * 64 + x0], v10 = p[y1 * 64 + x0];
    float v01 = p[y0 * 64 + x1], v11 = p[y1 * 64 + x1];
    float r0 = v00 * (1.f - wy) + v10 * wy;
    float r1 = v01 * (1.f - wy) + v11 * wy;
    float val = r0 * (1.f - wx) + r1 * wx;
    val = fminf(fmaxf(val, -1.f), 1.f);

    g_prior[tid] = val;
    out2[tid] = val;
}

// ============================================================
// K_proj: register-prefetched, 8 tiles (512 px = 2 rows) per block.
// Per tile: mma D[64,384] = X[64px,64c] @ Wh[64,384] + epilogue -> Abar/bx.
// sXc is k-major [c][px] swizzled; A fragment via ldmatrix.x4.trans.
// smem bytes: sWh 49152 | sXc 8192 | sA 18432 | sB 18432 | consts 4096
// ============================================================
#define SMEM_KP 98304
#define KTILES  8

__global__ __launch_bounds__(512) void kproj(
    const float* __restrict__ x,
    const float* __restrict__ lam_p,
    const float* __restrict__ alp_p)
{
    extern __shared__ char smc[];
    __half* sWh = (__half*)smc;
    __half* sXc = (__half*)(smc + 49152);           // [c=64][px=64] swizzled
    __half* sA  = (__half*)(smc + 57344);           // [128][72]
    __half* sB  = (__half*)(smc + 75776);
    float*  sps = (float*)(smc + 94208);            // [512]
    float*  sball = sps + 512;                      // [384]
    float*  sAc   = sball + 384;                    // [128]

    int tid = threadIdx.x;
    int pixB = blockIdx.x * (KTILES * 64);
    int bi = pixB >> 16;
    int hwB = pixB & 65535;
    const float* xg = x + (size_t)bi * CIN * PLANE + hwB;

    // weight staging (plain LDG, L2-resident after wave 1)
    {
        const uint4* gW = (const uint4*)g_Wh;
        uint4* sW = (uint4*)sWh;
        #pragma unroll
        for (int q = tid; q < 3072; q += 512) sW[q] = gW[q];
    }
    // constants
    sps[tid] = g_prior[pixB + tid];
    if (tid < 384) sball[tid] = g_ball[tid];
    if (tid >= 384) sAc[tid - 384] = g_Aconst[tid - 384];

    // x mapping: idx q in [0,1024): c = q>>4, seg = q&15 -> 4 floats at px seg*4
    int q0 = tid, q1 = tid + 512;
    int c0 = q0 >> 4, s0 = q0 & 15;
    int c1 = q1 >> 4, s1 = q1 & 15;

    // preload tile 0
    float4 xr0 = *(const float4*)(xg + (size_t)c0 * PLANE + s0 * 4);
    float4 xr1 = *(const float4*)(xg + (size_t)c1 * PLANE + s1 * 4);

    int w = tid >> 5, lane = tid & 31;
    int wp = w & 7, jw = w >> 3;
    int lr = lane & 15;
    int kr = lane & 7, sel = lane >> 3;
    float lam = *lam_p;
    float alp = *alp_p;

    unsigned a0 = s2u(&sXc[0]);   // base for A-fragment addressing

    #pragma unroll 1
    for (int t = 0; t < KTILES; t++) {
        // store-convert registers -> k-major swizzled sXc (8B stores)
        {
            __half2 h01 = __floats2half2_rn(xr0.x, xr0.y);
            __half2 h23 = __floats2half2_rn(xr0.z, xr0.w);
            uint2 u; u.x = *(unsigned*)&h01; u.y = *(unsigned*)&h23;
            *(uint2*)&sXc[c0 * 64 + (((s0 >> 1) ^ (c0 & 7)) << 3) + (s0 & 1) * 4] = u;
            h01 = __floats2half2_rn(xr1.x, xr1.y);
            h23 = __floats2half2_rn(xr1.z, xr1.w);
            u.x = *(unsigned*)&h01; u.y = *(unsigned*)&h23;
            *(uint2*)&sXc[c1 * 64 + (((s1 >> 1) ^ (c1 & 7)) << 3) + (s1 & 1) * 4] = u;
        }
        __syncthreads();

        // prefetch next tile into registers (consumed next iteration)
        if (t + 1 < KTILES) {
            const float* gt = xg + (t + 1) * 64;
            xr0 = *(const float4*)(gt + (size_t)c0 * PLANE + s0 * 4);
            xr1 = *(const float4*)(gt + (size_t)c1 * PLANE + s1 * 4);
        }

        // mma
        float acc[4][3][4];
        #pragma unroll
        for (int i = 0; i < 4; i++)
            #pragma unroll
            for (int j = 0; j < 3; j++)
                #pragma unroll
                for (int q = 0; q < 4; q++) acc[i][j][q] = 0.f;

        #pragma unroll
        for (int kc = 0; kc < 4; kc++) {
            unsigned a[4][4];
            #pragma unroll
            for (int ma = 0; ma < 4; ma++) {
                int krow = kc * 16 + ((sel >> 1) << 3) + kr;
                int mcol = ma * 16 + ((sel & 1) << 3);
                unsigned addr = a0 + (krow * 64 + (((mcol >> 3) ^ (krow & 7)) << 3)) * 2;
                ldsm_x4t(a[ma], addr);
            }
            unsigned b[3][2];
            #pragma unroll
            for (int r3 = 0; r3 < 3; r3++) {
                int na = r3 * 16 + wp * 2 + jw;
                int k = kc * 16 + lr;
                int nb = na * 8;
                unsigned addr = s2u(&sWh[k * 384 + (((nb >> 3) ^ (k & 7)) << 3)]);
                ldsm_x2t(b[r3], addr);
            }
            #pragma unroll
            for (int ma = 0; ma < 4; ma++)
                #pragma unroll
                for (int r3 = 0; r3 < 3; r3++)
                    mma16816(acc[ma][r3], a[ma], b[r3]);
        }

        // epilogue -> sA/sB
        #pragma unroll
        for (int i = 0; i < 2; i++) {
            int c = wp * 16 + jw * 8 + (lane & 3) * 2 + i;
            float bin = sball[3 * c];
            float bdl = sball[3 * c + 1];
            float bbb = sball[3 * c + 2];
            float Ac  = sAc[c];
            #pragma unroll
            for (int ma = 0; ma < 4; ma++) {
                #pragma unroll
                for (int rr = 0; rr < 2; rr++) {
                    int px = ma * 16 + (lane >> 2) + rr * 8;
                    int idx = rr * 2 + i;
                    float p = sps[t * 64 + px];
                    float xp   = acc[ma][0][idx] + bin;
                    float dpre = acc[ma][1][idx] + bdl + lam * p;
                    float delta = fmaxf(dpre, 0.f) + __logf(1.f + __expf(-fabsf(dpre)));
                    float bk = (acc[ma][2][idx] + bbb) * (1.f + alp * p);
                    sA[c * 72 + px] = __float2half(__expf(delta * Ac));
                    sB[c * 72 + px] = __float2half(delta * bk * xp);
                }
            }
        }
        __syncthreads();

        // coalesced global stores
        size_t ob = (size_t)bi * HID * PLANE + hwB + t * 64;
        #pragma unroll
        for (int q = tid; q < 1024; q += 512) {
            int c = q >> 3, p8 = (q & 7) * 8;
            *(uint4*)&g_Abar[ob + (size_t)c * PLANE + p8] = *(const uint4*)&sA[c * 72 + p8];
            *(uint4*)&g_bx[ob + (size_t)c * PLANE + p8]   = *(const uint4*)&sB[c * 72 + p8];
        }
    }
}

// ============================================================
// K_scanH: block = 256 rows x 64-col strip of one plane. Single DRAM pass.
// ============================================================
#define SMEM_SH (65536 + 4096)

__global__ __launch_bounds__(256) void kscanH()
{
    extern __shared__ __half2 sh2[];
    __half2* sA2 = sh2;              // [256][32] half2
    __half2* sB2 = sh2 + 8192;
    float2* AcS  = (float2*)(sh2 + 16384);   // [8][32]
    float2* BcS  = AcS + 256;

    int tid = threadIdx.x;
    int blk = blockIdx.x;
    size_t gbase = (size_t)(blk >> 2) * PLANE + (size_t)(blk & 3) * 64;
    size_t gb2 = gbase >> 1;

    {
        const __half* gA = g_Abar + gbase;
        const __half* gB = g_bx + gbase;
        #pragma unroll
        for (int q = tid; q < 2048; q += 256) {
            int r = q >> 3, g = q & 7;
            *(uint4*)&sA2[r * 32 + g * 4] = *(const uint4*)&gA[(size_t)r * 256 + g * 8];
            *(uint4*)&sB2[r * 32 + g * 4] = *(const uint4*)&gB[(size_t)r * 256 + g * 8];
        }
    }
    __syncthreads();

    int col2 = tid & 31;
    int chunk = tid >> 5;
    int r0 = chunk * 32;

    float2 Ac = make_float2(1.f, 1.f), Bc = make_float2(0.f, 0.f);
    #pragma unroll 8
    for (int r = 0; r < 32; r++) {
        float2 a = __half22float2(sA2[(r0 + r) * 32 + col2]);
        float2 b = __half22float2(sB2[(r0 + r) * 32 + col2]);
        Bc.x = fmaf(a.x, Bc.x, b.x); Bc.y = fmaf(a.y, Bc.y, b.y);
        Ac.x *= a.x; Ac.y *= a.y;
    }
    AcS[tid] = Ac; BcS[tid] = Bc;
    __syncthreads();

    float2 h = make_float2(0.f, 0.f);
    for (int k = 0; k < chunk; k++) {
        float2 A = AcS[k * 32 + col2];
        float2 B = BcS[k * 32 + col2];
        h.x = fmaf(A.x, h.x, B.x); h.y = fmaf(A.y, h.y, B.y);
    }

    __half2* S2 = (__half2*)g_sH;
    #pragma unroll 8
    for (int r = 0; r < 32; r++) {
        float2 a = __half22float2(sA2[(r0 + r) * 32 + col2]);
        float2 b = __half22float2(sB2[(r0 + r) * 32 + col2]);
        h.x = fmaf(a.x, h.x, b.x); h.y = fmaf(a.y, h.y, b.y);
        S2[gb2 + (size_t)(r0 + r) * 128 + col2] = __floats2half2_rn(h.x, h.y);
    }
}

// ============================================================
// K_scanWout: FUSED W-scan + sum(sH) + output GEMM + direct residual store.
// Block = one (batch, H-row): 128 channels x 256 px. 512 threads / 16 warps.
// Phase-1 loads software-pipelined (next channel fetched under scan chain).
// ============================================================
#define SMEM_SWO (82176)

__device__ __forceinline__ void unpack8h(uint4 u, float* f) {
    float2 t;
    t = __half22float2(*(__half2*)&u.x); f[0] = t.x; f[1] = t.y;
    t = __half22float2(*(__half2*)&u.y); f[2] = t.x; f[3] = t.y;
    t = __half22float2(*(__half2*)&u.z); f[4] = t.x; f[5] = t.y;
    t = __half22float2(*(__half2*)&u.w); f[6] = t.x; f[7] = t.y;
}

__global__ __launch_bounds__(512, 2) void kscanWout(
    const float* __restrict__ x,
    const float* __restrict__ b_out,
    const float* __restrict__ gam_p,
    float* __restrict__ out)
{
    extern __shared__ __half sm[];
    __half* sS  = sm;                       // [k=128][px=256] swizzled (64KB)
    __half* sWo = sm + 32768;               // [k=128][co=64] swizzled (16KB)
    float* sbo  = (float*)(sm + 40960);     // [64]

    int tid = threadIdx.x;
    int w = tid >> 5, lane = tid & 31;
    int bi = blockIdx.x >> 8;
    int y  = blockIdx.x & 255;

    {
        const uint4* gW = (const uint4*)g_Woh;
        uint4* sW = (uint4*)sWo;
        #pragma unroll
        for (int q = tid; q < 1024; q += 512) sW[q] = gW[q];
    }
    if (tid < 64) sbo[tid] = b_out[tid];

    // ---- Phase 1: W-scan 8 channels per warp (pipelined loads) ----
    size_t base = ((size_t)(bi * HID + w * 8)) * PLANE + (size_t)y * 256 + lane * 8;
    uint4 ua = *(const uint4*)(g_Abar + base);
    uint4 ub = *(const uint4*)(g_bx + base);
    uint4 us = *(const uint4*)(g_sH + base);

    #pragma unroll 1
    for (int i = 0; i < 8; i++) {
        float a[8], b[8], s[8];
        unpack8h(ua, a); unpack8h(ub, b); unpack8h(us, s);
        if (i < 7) {
            size_t nb = base + (size_t)(i + 1) * PLANE;
            ua = *(const uint4*)(g_Abar + nb);
            ub = *(const uint4*)(g_bx + nb);
            us = *(const uint4*)(g_sH + nb);
        }

        float Ac = 1.f, Bc = 0.f;
        #pragma unroll
        for (int j = 0; j < 8; j++) {
            Bc = fmaf(a[j], Bc, b[j]);
            Ac = a[j] * Ac;
        }
        #pragma unroll
        for (int d = 1; d < 32; d <<= 1) {
            float Ap = __shfl_up_sync(0xffffffffu, Ac, d);
            float Bp = __shfl_up_sync(0xffffffffu, Bc, d);
            if (lane >= d) {
                Bc = fmaf(Ac, Bp, Bc);
                Ac = Ac * Ap;
            }
        }
        float hin = __shfl_up_sync(0xffffffffu, Bc, 1);
        if (lane == 0) hin = 0.f;

        float h = hin, r[8];
        #pragma unroll
        for (int j = 0; j < 8; j++) {
            h = fmaf(a[j], h, b[j]);
            r[j] = h + s[j];
        }
        int c = w * 8 + i;
        union { uint4 u; __half2 hh[4]; } o;
        o.hh[0] = __floats2half2_rn(r[0], r[1]);
        o.hh[1] = __floats2half2_rn(r[2], r[3]);
        o.hh[2] = __floats2half2_rn(r[4], r[5]);
        o.hh[3] = __floats2half2_rn(r[6], r[7]);
        *(uint4*)&sS[c * 256 + ((lane ^ (c & 7)) << 3)] = o.u;
    }
    __syncthreads();

    // ---- Phase 2: GEMM. Warp w owns m-atom w (16 px), all 8 co-atoms. ----
    float acc[8][4];
    #pragma unroll
    for (int j = 0; j < 8; j++)
        #pragma unroll
        for (int q = 0; q < 4; q++) acc[j][q] = 0.f;

    int kr = lane & 7, sel = lane >> 3;
    #pragma unroll
    for (int kc = 0; kc < 8; kc++) {
        unsigned a[4];
        {
            int krow = kc * 16 + ((sel >> 1) << 3) + kr;
            int mcol = w * 16 + ((sel & 1) << 3);
            unsigned addr = s2u(&sS[krow * 256 + (((mcol >> 3) ^ (krow & 7)) << 3)]);
            ldsm_x4t(a, addr);
        }
        #pragma unroll
        for (int jp = 0; jp < 4; jp++) {
            unsigned b4[4];
            int k = kc * 16 + (lane & 15);
            int cog = jp * 2 + (lane >> 4);
            unsigned addr = s2u(&sWo[k * 64 + ((cog ^ (k & 7)) << 3)]);
            ldsm_x4t(b4, addr);
            mma16816(acc[jp * 2], a, b4);
            mma16816(acc[jp * 2 + 1], a, b4 + 2);
        }
    }

    // ---- direct epilogue: 32B-sector loads/stores, no smem staging ----
    float gam = *gam_p;
    int px = w * 16 + (lane >> 2);
    size_t rowb = (size_t)bi * CIN * PLANE + (size_t)y * 256;
    #pragma unroll
    for (int na = 0; na < 8; na++) {
        int co = na * 8 + (lane & 3) * 2;
        float bo0 = sbo[co], bo1 = sbo[co + 1];
        size_t b0 = rowb + (size_t)co * PLANE + px;
        out[b0]             = fmaf(gam, acc[na][0] + bo0, x[b0]);
        out[b0 + PLANE]     = fmaf(gam, acc[na][1] + bo1, x[b0 + PLANE]);
        out[b0 + 8]         = fmaf(gam, acc[na][2] + bo0, x[b0 + 8]);
        out[b0 + PLANE + 8] = fmaf(gam, acc[na][3] + bo1, x[b0 + PLANE + 8]);
    }
}

// ============================================================
extern "C" void kernel_launch(void* const* d_in, const int* in_sizes, int n_in,
                              void* d_out, int out_size)
{
    const float* x       = (const float*)d_in[0];
    const float* prior   = (const float*)d_in[1];
    const float* W_in    = (const float*)d_in[2];
    const float* b_in    = (const float*)d_in[3];
    const float* W_out   = (const float*)d_in[4];
    const float* b_out   = (const float*)d_in[5];
    const float* W_delta = (const float*)d_in[6];
    const float* b_delta = (const float*)d_in[7];
    const float* W_B     = (const float*)d_in[8];
    const float* b_B     = (const float*)d_in[9];
    const float* A_param = (const float*)d_in[10];
    const float* lam     = (const float*)d_in[11];
    const float* alp     = (const float*)d_in[12];
    const float* gam     = (const float*)d_in[13];
    float* out = (float*)d_out;

    cudaFuncSetAttribute(kproj, cudaFuncAttributeMaxDynamicSharedMemorySize, SMEM_KP);
    cudaFuncSetAttribute(kscanH, cudaFuncAttributeMaxDynamicSharedMemorySize, SMEM_SH);
    cudaFuncSetAttribute(kscanWout, cudaFuncAttributeMaxDynamicSharedMemorySize, SMEM_SWO);

    ksetup<<<130 + NPIX / 256, 256>>>(W_in, b_in, W_delta, b_delta, W_B, b_B,
                                      A_param, W_out, prior, out + OUT2);
    kproj<<<NPIX / (KTILES * 64), 512, SMEM_KP>>>(x, lam, alp);
    kscanH<<<2048, 256, SMEM_SH>>>();
    kscanWout<<<BATCH * 256, 512, SMEM_SWO>>>(x, b_out, gam, out);
}

// round 11
// speedup vs baseline: 3.9506x; 1.0546x over previous
#include <cuda_runtime.h>
#include <cuda_fp16.h>

#define BATCH 4
#define CIN   64
#define HID   128
#define PLANE 65536          // 256*256
#define NPIX  262144         // BATCH*PLANE
#define NELEM 33554432       // BATCH*HID*PLANE
#define OUT2  16777216       // BATCH*CIN*PLANE  (offset of prior_up in d_out)

// -------- scratch (static device globals: no allocation allowed) --------
__device__ float  g_ball[384];        // combined biases, index 3c+role
__device__ float  g_Aconst[HID];      // -exp(A_param)
__device__ float  g_prior[NPIX];      // clipped upsampled prior
__device__ __align__(16) __half g_Wh[64 * 384];   // fp16 proj weights [k][n], n=role*128+c, swizzled
__device__ __align__(16) __half g_Woh[128 * 64];  // fp16 W_out [k][co], swizzled
__device__ __half g_Abar[NELEM];
__device__ __half g_bx[NELEM];
__device__ __half g_sH[NELEM];        // H-scan result

__device__ __forceinline__ unsigned s2u(const void* p) {
    return (unsigned)__cvta_generic_to_shared(p);
}
__device__ __forceinline__ void ldsm_x4t(unsigned* r, unsigned addr) {
    asm volatile("ldmatrix.sync.aligned.m8n8.x4.trans.shared.b16 {%0,%1,%2,%3}, [%4];"
                 : "=r"(r[0]), "=r"(r[1]), "=r"(r[2]), "=r"(r[3]) : "r"(addr));
}
__device__ __forceinline__ void ldsm_x2t(unsigned* r, unsigned addr) {
    asm volatile("ldmatrix.sync.aligned.m8n8.x2.trans.shared.b16 {%0,%1}, [%2];"
                 : "=r"(r[0]), "=r"(r[1]) : "r"(addr));
}
__device__ __forceinline__ void mma16816(float* d, const unsigned* a, const unsigned* b) {
    asm volatile("mma.sync.aligned.m16n8k16.row.col.f32.f16.f16.f32 "
                 "{%0,%1,%2,%3},{%4,%5,%6,%7},{%8,%9},{%0,%1,%2,%3};"
                 : "+f"(d[0]), "+f"(d[1]), "+f"(d[2]), "+f"(d[3])
                 : "r"(a[0]), "r"(a[1]), "r"(a[2]), "r"(a[3]), "r"(b[0]), "r"(b[1]));
}

// ============================================================
// K_setup: blocks 0..129 = kpre, blocks 130.. = kprior
// ============================================================
__global__ __launch_bounds__(256) void ksetup(
    const float* __restrict__ W_in, const float* __restrict__ b_in,
    const float* __restrict__ W_delta, const float* __restrict__ b_delta,
    const float* __restrict__ W_B, const float* __restrict__ b_B,
    const float* __restrict__ A_param, const float* __restrict__ W_out,
    const float* __restrict__ prior, float* __restrict__ out2)
{
    if (blockIdx.x < 130) {
        int idx = blockIdx.x * 256 + threadIdx.x;
        if (idx < 384 * 64) {
            int r = idx >> 6, k = idx & 63;
            int c = r / 3, q = r - 3 * c;
            float v;
            if (q == 0) {
                v = W_in[c * 64 + k];
            } else {
                const float* Wm = (q == 1) ? W_delta : W_B;
                float s = 0.f;
                #pragma unroll 4
                for (int j = 0; j < 128; j++) s = fmaf(Wm[c * 128 + j], W_in[j * 64 + k], s);
                v = s;
            }
            int n = q * 128 + c;
            g_Wh[k * 384 + (((n >> 3) ^ (k & 7)) << 3) + (n & 7)] = __float2half(v);
        } else if (idx < 384 * 64 + 384) {
            int r = idx - 384 * 64;
            int c = r / 3, q = r - 3 * c;
            float v;
            if (q == 0) {
                v = b_in[c];
            } else {
                const float* Wm = (q == 1) ? W_delta : W_B;
                const float* bm = (q == 1) ? b_delta : b_B;
                float s = bm[c];
                #pragma unroll 4
                for (int j = 0; j < 128; j++) s = fmaf(Wm[c * 128 + j], b_in[j], s);
                v = s;
            }
            g_ball[r] = v;
        } else if (idx < 384 * 64 + 384 + HID) {
            int c = idx - (384 * 64 + 384);
            g_Aconst[c] = -expf(A_param[c]);
        } else if (idx < 384 * 64 + 384 + HID + 128 * 64) {
            int t = idx - (384 * 64 + 384 + HID);
            int k = t >> 6, co = t & 63;
            g_Woh[k * 64 + (((co >> 3) ^ (k & 7)) << 3) + (co & 7)] =
                __float2half(W_out[co * 128 + k]);
        }
        return;
    }
    int tid = (blockIdx.x - 130) * 256 + threadIdx.x;
    int bi = tid >> 16;
    int hw = tid & 65535;
    int oy = hw >> 8, ox = hw & 255;

    float fy = (float)(oy * 63) / 255.0f;
    float fx = (float)(ox * 63) / 255.0f;
    int y0 = (int)fy; int y1 = min(y0 + 1, 63);
    int x0 = (int)fx; int x1 = min(x0 + 1, 63);
    float wy = fy - (float)y0;
    float wx = fx - (float)x0;

    const float* p = prior + bi * 4096;
    float v00 = p[y0 * 64 + x0], v10 = p[y1 * 64 + x0];
    float v01 = p[y0 * 64 + x1], v11 = p[y1 * 64 + x1];
    float r0 = v00 * (1.f - wy) + v10 * wy;
    float r1 = v01 * (1.f - wy) + v11 * wy;
    float val = r0 * (1.f - wx) + r1 * wx;
    val = fminf(fmaxf(val, -1.f), 1.f);

    g_prior[tid] = val;
    out2[tid] = val;
}

// ============================================================
// K_proj: register-prefetched, 4 tiles/block, double-buffered sXc,
// ONE barrier per tile, direct sector-granular epilogue stores.
// smem bytes: sWh 49152 | sXc 2x8192 | sps 1024 | sball 1536 | sAc 512
// ============================================================
#define SMEM_KP 68608
#define KTILES  4

__global__ __launch_bounds__(512) void kproj(
    const float* __restrict__ x,
    const float* __restrict__ lam_p,
    const float* __restrict__ alp_p)
{
    extern __shared__ char smc[];
    __half* sWh = (__half*)smc;
    __half* sXc = (__half*)(smc + 49152);           // 2 bufs x [c=64][px=64] swizzled
    float*  sps = (float*)(smc + 65536);            // [256]
    float*  sball = sps + 256;                      // [384]
    float*  sAc   = sball + 384;                    // [128]

    int tid = threadIdx.x;
    int pixB = blockIdx.x * (KTILES * 64);
    int bi = pixB >> 16;
    int hwB = pixB & 65535;
    const float* xg = x + (size_t)bi * CIN * PLANE + hwB;

    // weight staging (plain LDG, L2-resident after wave 1)
    {
        const uint4* gW = (const uint4*)g_Wh;
        uint4* sW = (uint4*)sWh;
        #pragma unroll
        for (int q = tid; q < 3072; q += 512) sW[q] = gW[q];
    }
    // constants — OVERLAPPING predicates: full coverage of every array
    if (tid < 256) sps[tid] = g_prior[pixB + tid];
    if (tid < 384) sball[tid] = g_ball[tid];
    if (tid < 128) sAc[tid] = g_Aconst[tid];

    // x mapping: q in [0,1024): c = q>>4, seg = q&15 -> 4 floats at px seg*4
    int q0 = tid, q1 = tid + 512;
    int c0 = q0 >> 4, s0 = q0 & 15;
    int c1 = q1 >> 4, s1 = q1 & 15;

    // preload tile 0
    float4 xr0 = *(const float4*)(xg + (size_t)c0 * PLANE + s0 * 4);
    float4 xr1 = *(const float4*)(xg + (size_t)c1 * PLANE + s1 * 4);

    int w = tid >> 5, lane = tid & 31;
    int wp = w & 7, jw = w >> 3;
    int lr = lane & 15;
    int kr = lane & 7, sel = lane >> 3;
    float lam = *lam_p;
    float alp = *alp_p;

    unsigned aBase = s2u(sXc);

    #pragma unroll 1
    for (int t = 0; t < KTILES; t++) {
        // store-convert registers -> k-major swizzled sXc buffer (t&1)
        {
            __half* buf = sXc + (t & 1) * 4096;
            __half2 h01 = __floats2half2_rn(xr0.x, xr0.y);
            __half2 h23 = __floats2half2_rn(xr0.z, xr0.w);
            uint2 u; u.x = *(unsigned*)&h01; u.y = *(unsigned*)&h23;
            *(uint2*)&buf[c0 * 64 + (((s0 >> 1) ^ (c0 & 7)) << 3) + (s0 & 1) * 4] = u;
            h01 = __floats2half2_rn(xr1.x, xr1.y);
            h23 = __floats2half2_rn(xr1.z, xr1.w);
            u.x = *(unsigned*)&h01; u.y = *(unsigned*)&h23;
            *(uint2*)&buf[c1 * 64 + (((s1 >> 1) ^ (c1 & 7)) << 3) + (s1 & 1) * 4] = u;
        }
        __syncthreads();    // conv(t) visible to all; also covers weights/consts on t=0

        // prefetch next tile into registers (consumed next iteration)
        if (t + 1 < KTILES) {
            const float* gt = xg + (t + 1) * 64;
            xr0 = *(const float4*)(gt + (size_t)c0 * PLANE + s0 * 4);
            xr1 = *(const float4*)(gt + (size_t)c1 * PLANE + s1 * 4);
        }

        // mma
        float acc[4][3][4];
        #pragma unroll
        for (int i = 0; i < 4; i++)
            #pragma unroll
            for (int j = 0; j < 3; j++)
                #pragma unroll
                for (int q = 0; q < 4; q++) acc[i][j][q] = 0.f;

        unsigned a0 = aBase + (t & 1) * 8192;
        #pragma unroll
        for (int kc = 0; kc < 4; kc++) {
            unsigned a[4][4];
            #pragma unroll
            for (int ma = 0; ma < 4; ma++) {
                int krow = kc * 16 + ((sel >> 1) << 3) + kr;
                int mcol = ma * 16 + ((sel & 1) << 3);
                unsigned addr = a0 + (krow * 64 + (((mcol >> 3) ^ (krow & 7)) << 3)) * 2;
                ldsm_x4t(a[ma], addr);
            }
            unsigned b[3][2];
            #pragma unroll
            for (int r3 = 0; r3 < 3; r3++) {
                int na = r3 * 16 + wp * 2 + jw;
                int k = kc * 16 + lr;
                int nb = na * 8;
                unsigned addr = s2u(&sWh[k * 384 + (((nb >> 3) ^ (k & 7)) << 3)]);
                ldsm_x2t(b[r3], addr);
            }
            #pragma unroll
            for (int ma = 0; ma < 4; ma++)
                #pragma unroll
                for (int r3 = 0; r3 < 3; r3++)
                    mma16816(acc[ma][r3], a[ma], b[r3]);
        }

        // epilogue: direct sector-granular global stores (no staging)
        size_t ob = (size_t)bi * HID * PLANE + hwB + t * 64;
        #pragma unroll
        for (int i = 0; i < 2; i++) {
            int c = wp * 16 + jw * 8 + (lane & 3) * 2 + i;
            float bin = sball[3 * c];
            float bdl = sball[3 * c + 1];
            float bbb = sball[3 * c + 2];
            float Ac  = sAc[c];
            size_t cb = ob + (size_t)c * PLANE;
            #pragma unroll
            for (int ma = 0; ma < 4; ma++) {
                #pragma unroll
                for (int rr = 0; rr < 2; rr++) {
                    int px = ma * 16 + (lane >> 2) + rr * 8;
                    int idx = rr * 2 + i;
                    float p = sps[t * 64 + px];
                    float xp   = acc[ma][0][idx] + bin;
                    float dpre = acc[ma][1][idx] + bdl + lam * p;
                    float delta = fmaxf(dpre, 0.f) + __logf(1.f + __expf(-fabsf(dpre)));
                    float bk = (acc[ma][2][idx] + bbb) * (1.f + alp * p);
                    g_Abar[cb + px] = __float2half(__expf(delta * Ac));
                    g_bx[cb + px]   = __float2half(delta * bk * xp);
                }
            }
        }
        // no second barrier: next conv writes the other sXc buffer
    }
}

// ============================================================
// K_scanH: block = 256 rows x 64-col strip of one plane. Single DRAM pass.
// ============================================================
#define SMEM_SH (65536 + 4096)

__global__ __launch_bounds__(256) void kscanH()
{
    extern __shared__ __half2 sh2[];
    __half2* sA2 = sh2;              // [256][32] half2
    __half2* sB2 = sh2 + 8192;
    float2* AcS  = (float2*)(sh2 + 16384);   // [8][32]
    float2* BcS  = AcS + 256;

    int tid = threadIdx.x;
    int blk = blockIdx.x;
    size_t gbase = (size_t)(blk >> 2) * PLANE + (size_t)(blk & 3) * 64;
    size_t gb2 = gbase >> 1;

    {
        const __half* gA = g_Abar + gbase;
        const __half* gB = g_bx + gbase;
        #pragma unroll
        for (int q = tid; q < 2048; q += 256) {
            int r = q >> 3, g = q & 7;
            *(uint4*)&sA2[r * 32 + g * 4] = *(const uint4*)&gA[(size_t)r * 256 + g * 8];
            *(uint4*)&sB2[r * 32 + g * 4] = *(const uint4*)&gB[(size_t)r * 256 + g * 8];
        }
    }
    __syncthreads();

    int col2 = tid & 31;
    int chunk = tid >> 5;
    int r0 = chunk * 32;

    float2 Ac = make_float2(1.f, 1.f), Bc = make_float2(0.f, 0.f);
    #pragma unroll 8
    for (int r = 0; r < 32; r++) {
        float2 a = __half22float2(sA2[(r0 + r) * 32 + col2]);
        float2 b = __half22float2(sB2[(r0 + r) * 32 + col2]);
        Bc.x = fmaf(a.x, Bc.x, b.x); Bc.y = fmaf(a.y, Bc.y, b.y);
        Ac.x *= a.x; Ac.y *= a.y;
    }
    AcS[tid] = Ac; BcS[tid] = Bc;
    __syncthreads();

    float2 h = make_float2(0.f, 0.f);
    for (int k = 0; k < chunk; k++) {
        float2 A = AcS[k * 32 + col2];
        float2 B = BcS[k * 32 + col2];
        h.x = fmaf(A.x, h.x, B.x); h.y = fmaf(A.y, h.y, B.y);
    }

    __half2* S2 = (__half2*)g_sH;
    #pragma unroll 8
    for (int r = 0; r < 32; r++) {
        float2 a = __half22float2(sA2[(r0 + r) * 32 + col2]);
        float2 b = __half22float2(sB2[(r0 + r) * 32 + col2]);
        h.x = fmaf(a.x, h.x, b.x); h.y = fmaf(a.y, h.y, b.y);
        S2[gb2 + (size_t)(r0 + r) * 128 + col2] = __floats2half2_rn(h.x, h.y);
    }
}

// ============================================================
// K_scanWout: FUSED W-scan + sum(sH) + output GEMM + direct residual store.
// ============================================================
#define SMEM_SWO (82176)

__device__ __forceinline__ void unpack8h(uint4 u, float* f) {
    float2 t;
    t = __half22float2(*(__half2*)&u.x); f[0] = t.x; f[1] = t.y;
    t = __half22float2(*(__half2*)&u.y); f[2] = t.x; f[3] = t.y;
    t = __half22float2(*(__half2*)&u.z); f[4] = t.x; f[5] = t.y;
    t = __half22float2(*(__half2*)&u.w); f[6] = t.x; f[7] = t.y;
}

__global__ __launch_bounds__(512, 2) void kscanWout(
    const float* __restrict__ x,
    const float* __restrict__ b_out,
    const float* __restrict__ gam_p,
    float* __restrict__ out)
{
    extern __shared__ __half sm[];
    __half* sS  = sm;                       // [k=128][px=256] swizzled (64KB)
    __half* sWo = sm + 32768;               // [k=128][co=64] swizzled (16KB)
    float* sbo  = (float*)(sm + 40960);     // [64]

    int tid = threadIdx.x;
    int w = tid >> 5, lane = tid & 31;
    int bi = blockIdx.x >> 8;
    int y  = blockIdx.x & 255;

    {
        const uint4* gW = (const uint4*)g_Woh;
        uint4* sW = (uint4*)sWo;
        #pragma unroll
        for (int q = tid; q < 1024; q += 512) sW[q] = gW[q];
    }
    if (tid < 64) sbo[tid] = b_out[tid];

    // ---- Phase 1: W-scan 8 channels per warp (pipelined loads) ----
    size_t base = ((size_t)(bi * HID + w * 8)) * PLANE + (size_t)y * 256 + lane * 8;
    uint4 ua = *(const uint4*)(g_Abar + base);
    uint4 ub = *(const uint4*)(g_bx + base);
    uint4 us = *(const uint4*)(g_sH + base);

    #pragma unroll 1
    for (int i = 0; i < 8; i++) {
        float a[8], b[8], s[8];
        unpack8h(ua, a); unpack8h(ub, b); unpack8h(us, s);
        if (i < 7) {
            size_t nb = base + (size_t)(i + 1) * PLANE;
            ua = *(const uint4*)(g_Abar + nb);
            ub = *(const uint4*)(g_bx + nb);
            us = *(const uint4*)(g_sH + nb);
        }

        float Ac = 1.f, Bc = 0.f;
        #pragma unroll
        for (int j = 0; j < 8; j++) {
            Bc = fmaf(a[j], Bc, b[j]);
            Ac = a[j] * Ac;
        }
        #pragma unroll
        for (int d = 1; d < 32; d <<= 1) {
            float Ap = __shfl_up_sync(0xffffffffu, Ac, d);
            float Bp = __shfl_up_sync(0xffffffffu, Bc, d);
            if (lane >= d) {
                Bc = fmaf(Ac, Bp, Bc);
                Ac = Ac * Ap;
            }
        }
        float hin = __shfl_up_sync(0xffffffffu, Bc, 1);
        if (lane == 0) hin = 0.f;

        float h = hin, r[8];
        #pragma unroll
        for (int j = 0; j < 8; j++) {
            h = fmaf(a[j], h, b[j]);
            r[j] = h + s[j];
        }
        int c = w * 8 + i;
        union { uint4 u; __half2 hh[4]; } o;
        o.hh[0] = __floats2half2_rn(r[0], r[1]);
        o.hh[1] = __floats2half2_rn(r[2], r[3]);
        o.hh[2] = __floats2half2_rn(r[4], r[5]);
        o.hh[3] = __floats2half2_rn(r[6], r[7]);
        *(uint4*)&sS[c * 256 + ((lane ^ (c & 7)) << 3)] = o.u;
    }
    __syncthreads();

    // ---- Phase 2: GEMM. Warp w owns m-atom w (16 px), all 8 co-atoms. ----
    float acc[8][4];
    #pragma unroll
    for (int j = 0; j < 8; j++)
        #pragma unroll
        for (int q = 0; q < 4; q++) acc[j][q] = 0.f;

    int kr = lane & 7, sel = lane >> 3;
    #pragma unroll
    for (int kc = 0; kc < 8; kc++) {
        unsigned a[4];
        {
            int krow = kc * 16 + ((sel >> 1) << 3) + kr;
            int mcol = w * 16 + ((sel & 1) << 3);
            unsigned addr = s2u(&sS[krow * 256 + (((mcol >> 3) ^ (krow & 7)) << 3)]);
            ldsm_x4t(a, addr);
        }
        #pragma unroll
        for (int jp = 0; jp < 4; jp++) {
            unsigned b4[4];
            int k = kc * 16 + (lane & 15);
            int cog = jp * 2 + (lane >> 4);
            unsigned addr = s2u(&sWo[k * 64 + ((cog ^ (k & 7)) << 3)]);
            ldsm_x4t(b4, addr);
            mma16816(acc[jp * 2], a, b4);
            mma16816(acc[jp * 2 + 1], a, b4 + 2);
        }
    }

    // ---- direct epilogue ----
    float gam = *gam_p;
    int px = w * 16 + (lane >> 2);
    size_t rowb = (size_t)bi * CIN * PLANE + (size_t)y * 256;
    #pragma unroll
    for (int na = 0; na < 8; na++) {
        int co = na * 8 + (lane & 3) * 2;
        float bo0 = sbo[co], bo1 = sbo[co + 1];
        size_t b0 = rowb + (size_t)co * PLANE + px;
        out[b0]             = fmaf(gam, acc[na][0] + bo0, x[b0]);
        out[b0 + PLANE]     = fmaf(gam, acc[na][1] + bo1, x[b0 + PLANE]);
        out[b0 + 8]         = fmaf(gam, acc[na][2] + bo0, x[b0 + 8]);
        out[b0 + PLANE + 8] = fmaf(gam, acc[na][3] + bo1, x[b0 + PLANE + 8]);
    }
}

// ============================================================
extern "C" void kernel_launch(void* const* d_in, const int* in_sizes, int n_in,
                              void* d_out, int out_size)
{
    const float* x       = (const float*)d_in[0];
    const float* prior   = (const float*)d_in[1];
    const float* W_in    = (const float*)d_in[2];
    const float* b_in    = (const float*)d_in[3];
    const float* W_out   = (const float*)d_in[4];
    const float* b_out   = (const float*)d_in[5];
    const float* W_delta = (const float*)d_in[6];
    const float* b_delta = (const float*)d_in[7];
    const float* W_B     = (const float*)d_in[8];
    const float* b_B     = (const float*)d_in[9];
    const float* A_param = (const float*)d_in[10];
    const float* lam     = (const float*)d_in[11];
    const float* alp     = (const float*)d_in[12];
    const float* gam     = (const float*)d_in[13];
    float* out = (float*)d_out;

    cudaFuncSetAttribute(kproj, cudaFuncAttributeMaxDynamicSharedMemorySize, SMEM_KP);
    cudaFuncSetAttribute(kscanH, cudaFuncAttributeMaxDynamicSharedMemorySize, SMEM_SH);
    cudaFuncSetAttribute(kscanWout, cudaFuncAttributeMaxDynamicSharedMemorySize, SMEM_SWO);

    ksetup<<<130 + NPIX / 256, 256>>>(W_in, b_in, W_delta, b_delta, W_B, b_B,
                                      A_param, W_out, prior, out + OUT2);
    kproj<<<NPIX / (KTILES * 64), 512, SMEM_KP>>>(x, lam, alp);
    kscanH<<<2048, 256, SMEM_SH>>>();
    kscanWout<<<BATCH * 256, 512, SMEM_SWO>>>(x, b_out, gam, out);
}